// round 7
// baseline (speedup 1.0000x reference)
#include <cuda_runtime.h>
#include <cuda_bf16.h>
#include <cstdint>
#include <math.h>

#define NROWS 32768
#define FDIM  128
#define KDIM  64
#define MNBR  32
#define NTILES (NROWS/4)

// Scratch (allocation-free rule: __device__ globals)
__device__ float g_xi [NROWS*FDIM];
__device__ float g_xjp[NROWS*FDIM];
__device__ float g_m0 [NROWS*FDIM];
__device__ float g_m1 [NROWS*FDIM];
__device__ float g_t  [NROWS*FDIM];

__device__ __forceinline__ float sspf(float a) {
    return fmaxf(a, 0.0f) + log1pf(expf(-fabsf(a))) - 0.69314718055994530942f;
}

// ---------------- mma.sync helpers ----------------
__device__ __forceinline__ uint32_t s2u(const void* p) {
    uint32_t a;
    asm("{ .reg .u64 t; cvta.to.shared.u64 t, %1; cvt.u32.u64 %0, t; }" : "=r"(a) : "l"(p));
    return a;
}

#define LDM_X4(r, addr) \
    asm volatile("ldmatrix.sync.aligned.m8n8.x4.shared.b16 {%0,%1,%2,%3}, [%4];" \
        : "=r"((r)[0]), "=r"((r)[1]), "=r"((r)[2]), "=r"((r)[3]) : "r"(addr))

#define MMA_BF16(d, a, b0, b1) \
    asm volatile("mma.sync.aligned.m16n8k16.row.col.f32.bf16.bf16.f32 " \
        "{%0,%1,%2,%3}, {%4,%5,%6,%7}, {%8,%9}, {%0,%1,%2,%3};" \
        : "+f"((d)[0]), "+f"((d)[1]), "+f"((d)[2]), "+f"((d)[3]) \
        : "r"((a)[0]), "r"((a)[1]), "r"((a)[2]), "r"((a)[3]), "r"(b0), "r"(b1))

__device__ __forceinline__ void bf16_split4(float4 v, __nv_bfloat16* H, __nv_bfloat16* L) {
    __nv_bfloat16 h0 = __float2bfloat16(v.x), h1 = __float2bfloat16(v.y),
                  h2 = __float2bfloat16(v.z), h3 = __float2bfloat16(v.w);
    *(__nv_bfloat162*)(H)     = __nv_bfloat162(h0, h1);
    *(__nv_bfloat162*)(H + 2) = __nv_bfloat162(h2, h3);
    *(__nv_bfloat162*)(L)     = __nv_bfloat162(__float2bfloat16(v.x - __bfloat162float(h0)),
                                               __float2bfloat16(v.y - __bfloat162float(h1)));
    *(__nv_bfloat162*)(L + 2) = __nv_bfloat162(__float2bfloat16(v.z - __bfloat162float(h2)),
                                               __float2bfloat16(v.w - __bfloat162float(h3)));
}

// =================================================================================
// Tensor-core row GEMM: 256 threads, 64-row x 128-col tile, 2 CTAs/SM.
// out[n,f] = epi( sum_k act(in[n,k]) * W[f,k] + b[f] )
// =================================================================================
#define TG_WH    0u
#define TG_WL    34816u
#define TG_U     69632u           // AH (64x136x2=17408); AL at +17408; slab 64x132 fp32 unions
#define TG_AH    TG_U
#define TG_AL    (TG_U + 17408u)
#define TG_BIAS  104448u          // float[128]
#define TG_MUL   104960u          // float[128]
#define TG_TOTAL 105472u
#define TG_SLABS 132

template<bool IN_SSP, bool ADD, bool MULVEC>
__global__ __launch_bounds__(256, 2) void trowgemm(
    const float* __restrict__ in, const float* __restrict__ W,
    const float* __restrict__ bias, const float* __restrict__ addp,
    const float* __restrict__ mulv, float* __restrict__ out)
{
    extern __shared__ char smem[];
    __nv_bfloat16* WH = (__nv_bfloat16*)(smem + TG_WH);
    __nv_bfloat16* WL = (__nv_bfloat16*)(smem + TG_WL);
    __nv_bfloat16* AH = (__nv_bfloat16*)(smem + TG_AH);
    __nv_bfloat16* AL = (__nv_bfloat16*)(smem + TG_AL);
    float* slab = (float*)(smem + TG_U);
    float* b_sm = (float*)(smem + TG_BIAS);
    float* u_sm = (float*)(smem + TG_MUL);

    const int tid = threadIdx.x;
    const int wid = tid >> 5, lid = tid & 31;
    const uint32_t sb = s2u(smem);

    // weights: 128x128 fp32 -> hi/lo bf16 [row][136]
    #pragma unroll
    for (int i = 0; i < 16; i++) {
        int fidx = tid + 256 * i;            // float4 idx over 4096
        float4 v = ((const float4*)W)[fidx];
        int row = fidx >> 5, c = (fidx & 31) * 4;
        bf16_split4(v, WH + row * 136 + c, WL + row * 136 + c);
    }
    if (tid < 128) {
        b_sm[tid] = bias[tid];
        u_sm[tid] = MULVEC ? mulv[tid] : 0.0f;
    }

    const int r0 = blockIdx.x * 64;

    // input tile 64x128: act + split
    #pragma unroll
    for (int i = 0; i < 8; i++) {
        int fidx = tid + 256 * i;            // float4 idx over 2048
        float4 v = ((const float4*)(in + (size_t)r0 * FDIM))[fidx];
        if (IN_SSP) { v.x = sspf(v.x); v.y = sspf(v.y); v.z = sspf(v.z); v.w = sspf(v.w); }
        int row = fidx >> 5, c = (fidx & 31) * 4;
        bf16_split4(v, AH + row * 136 + c, AL + row * 136 + c);
    }
    __syncthreads();

    // per-lane ldmatrix byte offsets (row stride 272 B)
    const uint32_t aL = (((lid & 7) + (lid & 8)) * 136 + ((lid & 16) ? 8 : 0)) * 2;
    const uint32_t bL = (((lid & 7) + ((lid & 16) >> 1)) * 136 + ((lid & 8) ? 8 : 0)) * 2;
    const int wr = wid & 1, wc = wid >> 1;   // warp: 32 rows x 32 cols

    float acc[2][4][4];
    #pragma unroll
    for (int mt = 0; mt < 2; mt++)
        #pragma unroll
        for (int nb = 0; nb < 4; nb++)
            #pragma unroll
            for (int c = 0; c < 4; c++) acc[mt][nb][c] = 0.f;

    #pragma unroll
    for (int kk = 0; kk < 8; kk++) {
        const uint32_t kb = (uint32_t)kk * 32;
        uint32_t ah[2][4], al[2][4], bh[2][4], bl[2][4];
        #pragma unroll
        for (int mt = 0; mt < 2; mt++) {
            uint32_t ro = (uint32_t)(32*wr + 16*mt) * 272 + kb;
            LDM_X4(ah[mt], sb + TG_AH + aL + ro);
            LDM_X4(al[mt], sb + TG_AL + aL + ro);
        }
        #pragma unroll
        for (int np = 0; np < 2; np++) {
            uint32_t no = (uint32_t)(32*wc + 16*np) * 272 + kb;
            LDM_X4(bh[np], sb + TG_WH + bL + no);
            LDM_X4(bl[np], sb + TG_WL + bL + no);
        }
        #pragma unroll
        for (int mt = 0; mt < 2; mt++)
            #pragma unroll
            for (int np = 0; np < 2; np++) {
                MMA_BF16(acc[mt][2*np],   ah[mt], bh[np][0], bh[np][1]);
                MMA_BF16(acc[mt][2*np+1], ah[mt], bh[np][2], bh[np][3]);
                MMA_BF16(acc[mt][2*np],   ah[mt], bl[np][0], bl[np][1]);
                MMA_BF16(acc[mt][2*np+1], ah[mt], bl[np][2], bl[np][3]);
                MMA_BF16(acc[mt][2*np],   al[mt], bh[np][0], bh[np][1]);
                MMA_BF16(acc[mt][2*np+1], al[mt], bh[np][2], bh[np][3]);
            }
    }
    __syncthreads();   // A reads done -> union becomes slab

    {
        const int g = lid >> 2, t = lid & 3;
        #pragma unroll
        for (int mt = 0; mt < 2; mt++)
            #pragma unroll
            for (int nb = 0; nb < 4; nb++) {
                int e = 32*wr + 16*mt + g;
                int c = 32*wc + 8*nb + 2*t;
                *(float2*)&slab[e * TG_SLABS + c] = make_float2(acc[mt][nb][0], acc[mt][nb][1]);
                *(float2*)&slab[(e+8) * TG_SLABS + c] = make_float2(acc[mt][nb][2], acc[mt][nb][3]);
            }
    }
    __syncthreads();

    // coalesced epilogue: 64x128
    #pragma unroll
    for (int i = 0; i < 32; i++) {
        int idx = tid + 256 * i;
        int row = idx >> 7, col = idx & 127;
        float o = slab[row * TG_SLABS + col] + b_sm[col];
        if (ADD) {
            float av = addp[(size_t)(r0 + row) * FDIM + col];
            o += MULVEC ? av * u_sm[col] : av;
        }
        out[(size_t)(r0 + row) * FDIM + col] = o;
    }
}

// =================================================================================
// Fused edge-filter GEMM + gather + attention: 256 threads, 2 CTAs/SM (R3 math)
// =================================================================================
#define OFF_BH   0u
#define OFF_BL   18432u
#define OFF_U    36864u          // AH; AL at +18432; fp32 slab[128][132]=67584 unions
#define OFF_AH   OFF_U
#define OFF_AL   (OFF_U + 18432u)
#define OFF_XI   104448u         // float[512]
#define OFF_PART 106496u         // float[1024]
#define OFF_ATT  110592u         // float[128]
#define OFF_JIDX 111104u         // int[128]
#define SM_TOTAL 111616u
#define SLAB_STRIDE 132

__global__ void __launch_bounds__(256, 2) attn_mma(
    const float* __restrict__ rbf, const int* __restrict__ idxj,
    const float* __restrict__ k2f, const float* __restrict__ xi,
    const float* __restrict__ xjp, float* __restrict__ mout)
{
    extern __shared__ char smem[];
    __nv_bfloat16* AH = (__nv_bfloat16*)(smem + OFF_AH);
    __nv_bfloat16* AL = (__nv_bfloat16*)(smem + OFF_AL);
    __nv_bfloat16* BH = (__nv_bfloat16*)(smem + OFF_BH);
    __nv_bfloat16* BL = (__nv_bfloat16*)(smem + OFF_BL);
    float* slab   = (float*)(smem + OFF_U);
    float* xi_sm  = (float*)(smem + OFF_XI);
    float* part   = (float*)(smem + OFF_PART);
    float* att_sm = (float*)(smem + OFF_ATT);
    int*   jidx   = (int*)  (smem + OFF_JIDX);

    const int tid = threadIdx.x;
    const int wid = tid >> 5, lid = tid & 31;
    const uint32_t sb = s2u(smem);

    // B = k2f [128 f x 64 k], hi/lo split, loaded once
    #pragma unroll
    for (int i = 0; i < 8; i++) {
        int fidx = tid + 256 * i;            // float4 idx over 2048
        float4 v = ((const float4*)k2f)[fidx];
        int row = fidx >> 4, c = (fidx & 15) * 4;
        bf16_split4(v, BH + row*72 + c, BL + row*72 + c);
    }
    __syncthreads();

    const uint32_t aL = ((((lid & 7) + (lid & 8)) * 72) + ((lid & 16) ? 8 : 0)) * 2;
    const uint32_t bL = ((((lid & 7) + ((lid & 16) >> 1)) * 72) + ((lid & 8) ? 8 : 0)) * 2;
    const int wr = wid & 3, wc = wid >> 2;   // warp: 32 edges x 64 cols

    const int f  = tid & 127;
    const int q  = f >> 5;
    const int e0 = tid >> 7;                 // 0 or 1

    for (int tile = blockIdx.x; tile < NTILES; tile += gridDim.x) {
        const int n0 = tile * 4;

        const float4* rp = (const float4*)(rbf + (size_t)tile * 8192);
        #pragma unroll
        for (int i = 0; i < 8; i++) {
            int fidx = tid + 256 * i;
            float4 v = rp[fidx];
            int row = fidx >> 4, c = (fidx & 15) * 4;
            bf16_split4(v, AH + row*72 + c, AL + row*72 + c);
        }
        if (tid < 128) jidx[tid] = idxj[tile * 128 + tid];
        #pragma unroll
        for (int i = 0; i < 2; i++) {
            int ix = tid + 256 * i;
            xi_sm[ix] = xi[(size_t)n0 * FDIM + ix];
        }
        __syncthreads();

        float acc[2][8][4];
        #pragma unroll
        for (int mt = 0; mt < 2; mt++)
            #pragma unroll
            for (int nb = 0; nb < 8; nb++)
                #pragma unroll
                for (int c = 0; c < 4; c++) acc[mt][nb][c] = 0.f;

        #pragma unroll
        for (int kk = 0; kk < 4; kk++) {
            const uint32_t kb = (uint32_t)kk * 32;
            uint32_t ah[2][4], al[2][4];
            #pragma unroll
            for (int mt = 0; mt < 2; mt++) {
                uint32_t ro = (uint32_t)(32*wr + 16*mt) * 144 + kb;
                LDM_X4(ah[mt], sb + OFF_AH + aL + ro);
                LDM_X4(al[mt], sb + OFF_AL + aL + ro);
            }
            #pragma unroll
            for (int np = 0; np < 4; np++) {
                uint32_t bh[4], bl[4];
                uint32_t no = (uint32_t)(64*wc + 16*np) * 144 + kb;
                LDM_X4(bh, sb + OFF_BH + bL + no);
                LDM_X4(bl, sb + OFF_BL + bL + no);
                #pragma unroll
                for (int mt = 0; mt < 2; mt++) {
                    MMA_BF16(acc[mt][2*np],   ah[mt], bh[0], bh[1]);
                    MMA_BF16(acc[mt][2*np+1], ah[mt], bh[2], bh[3]);
                    MMA_BF16(acc[mt][2*np],   ah[mt], bl[0], bl[1]);
                    MMA_BF16(acc[mt][2*np+1], ah[mt], bl[2], bl[3]);
                    MMA_BF16(acc[mt][2*np],   al[mt], bh[0], bh[1]);
                    MMA_BF16(acc[mt][2*np+1], al[mt], bh[2], bh[3]);
                }
            }
        }
        __syncthreads();   // A reads done -> union becomes slab

        {
            const int g = lid >> 2, t = lid & 3;
            #pragma unroll
            for (int mt = 0; mt < 2; mt++)
                #pragma unroll
                for (int nb = 0; nb < 8; nb++) {
                    int e = 32*wr + 16*mt + g;
                    int c = 64*wc + 8*nb + 2*t;
                    *(float2*)&slab[e * SLAB_STRIDE + c] =
                        make_float2(acc[mt][nb][0], acc[mt][nb][1]);
                    *(float2*)&slab[(e + 8) * SLAB_STRIDE + c] =
                        make_float2(acc[mt][nb][2], acc[mt][nb][3]);
                }
        }
        __syncthreads();

        // gather + product + logit partials, two 32-reg batches (caps regs for occ 2)
        float lacc[4] = {0.f, 0.f, 0.f, 0.f};
        #pragma unroll
        for (int b = 0; b < 2; b++) {
            float xp[32];
            #pragma unroll
            for (int i = 0; i < 32; i++) {
                int e = 2 * (32*b + i) + e0;
                xp[i] = xjp[(size_t)jidx[e] * FDIM + f];
            }
            #pragma unroll
            for (int i = 0; i < 32; i++) {
                const int ii = 32*b + i;
                const int e = 2*ii + e0;
                const int a = ii >> 4;
                const int m = e & 31;
                float p = slab[e * SLAB_STRIDE + f] * xp[i];
                slab[e * SLAB_STRIDE + f] = p;
                lacc[a] += xi_sm[a * FDIM + 4*m + q] * p;
            }
        }
        #pragma unroll
        for (int a = 0; a < 4; a++)
            part[wid * 128 + a * 32 + lid] = lacc[a];
        __syncthreads();

        if (wid < 4) {
            float lg = 0.f;
            #pragma unroll
            for (int w2 = 0; w2 < 8; w2++) lg += part[w2 * 128 + wid * 32 + lid];
            float mx = lg;
            #pragma unroll
            for (int o = 16; o; o >>= 1) mx = fmaxf(mx, __shfl_xor_sync(0xffffffffu, mx, o));
            float ex = expf(lg - mx);
            float smv = ex;
            #pragma unroll
            for (int o = 16; o; o >>= 1) smv += __shfl_xor_sync(0xffffffffu, smv, o);
            att_sm[wid * 32 + lid] = ex / smv;
        }
        __syncthreads();

        // attention-weighted sum, products re-read from slab
        float pacc[4] = {0.f, 0.f, 0.f, 0.f};
        #pragma unroll
        for (int ii = 0; ii < 64; ii++) {
            const int e = 2*ii + e0;
            const int a = ii >> 4;
            const int m = e & 31;
            pacc[a] += att_sm[a * 32 + m] * slab[e * SLAB_STRIDE + f];
        }
        #pragma unroll
        for (int a = 0; a < 4; a++)
            part[e0 * 512 + a * 128 + f] = pacc[a];
        __syncthreads();

        #pragma unroll
        for (int i2 = 0; i2 < 2; i2++) {
            int ix = tid + 256 * i2;
            mout[(size_t)n0 * FDIM + ix] = xi_sm[ix] + part[ix] + part[512 + ix];
        }
        __syncthreads();
    }
}

extern "C" void kernel_launch(void* const* d_in, const int* in_sizes, int n_in,
                              void* d_out, int out_size)
{
    const float* x    = (const float*)d_in[0];
    const float* rbf  = (const float*)d_in[1];
    const int*   idxj = (const int*)  d_in[3];
    const float* k2f  = (const float*)d_in[4];
    const float* wi   = (const float*)d_in[5];
    const float* bi   = (const float*)d_in[6];
    const float* wj   = (const float*)d_in[7];
    const float* bj   = (const float*)d_in[8];
    const float* rw1  = (const float*)d_in[9];
    const float* rb1  = (const float*)d_in[10];
    const float* rw2  = (const float*)d_in[11];
    const float* rb2  = (const float*)d_in[12];
    const float* wd   = (const float*)d_in[13];
    const float* bd   = (const float*)d_in[14];
    const float* u    = (const float*)d_in[15];
    float* out = (float*)d_out;

    float *xi_p, *xjp_p, *m0_p, *m1_p, *t_p;
    cudaGetSymbolAddress((void**)&xi_p,  g_xi);
    cudaGetSymbolAddress((void**)&xjp_p, g_xjp);
    cudaGetSymbolAddress((void**)&m0_p,  g_m0);
    cudaGetSymbolAddress((void**)&m1_p,  g_m1);
    cudaGetSymbolAddress((void**)&t_p,   g_t);

    static int nsm = 0;
    if (nsm == 0) {
        cudaDeviceGetAttribute(&nsm, cudaDevAttrMultiProcessorCount, 0);
        if (nsm <= 0) nsm = 148;
        cudaFuncSetAttribute(attn_mma, cudaFuncAttributeMaxDynamicSharedMemorySize, SM_TOTAL);
        cudaFuncSetAttribute(trowgemm<true,  false, false>, cudaFuncAttributeMaxDynamicSharedMemorySize, TG_TOTAL);
        cudaFuncSetAttribute(trowgemm<false, true,  false>, cudaFuncAttributeMaxDynamicSharedMemorySize, TG_TOTAL);
        cudaFuncSetAttribute(trowgemm<true,  true,  true >, cudaFuncAttributeMaxDynamicSharedMemorySize, TG_TOTAL);
    }

    const int TG_GRID = NROWS / 64;   // 512

    trowgemm<true,  false, false><<<TG_GRID, 256, TG_TOTAL>>>(x,    wi, bi, nullptr, nullptr, xi_p);
    trowgemm<true,  false, false><<<TG_GRID, 256, TG_TOTAL>>>(x,    wj, bj, nullptr, nullptr, xjp_p);

    attn_mma<<<2 * nsm, 256, SM_TOTAL>>>(rbf, idxj, k2f, xi_p, xjp_p, m0_p);

    trowgemm<true,  false, false><<<TG_GRID, 256, TG_TOTAL>>>(m0_p, rw1,             rb1,        nullptr, nullptr, t_p);
    trowgemm<false, true,  false><<<TG_GRID, 256, TG_TOTAL>>>(t_p,  rw2,             rb2,        m0_p,    nullptr, m1_p);
    trowgemm<true,  false, false><<<TG_GRID, 256, TG_TOTAL>>>(m1_p, rw1 + FDIM*FDIM, rb1 + FDIM, nullptr, nullptr, t_p);
    trowgemm<false, true,  false><<<TG_GRID, 256, TG_TOTAL>>>(t_p,  rw2 + FDIM*FDIM, rb2 + FDIM, m1_p,    nullptr, m0_p);
    trowgemm<true,  true,  true ><<<TG_GRID, 256, TG_TOTAL>>>(m0_p, wd,              bd,         x,       u,       out);
}

// round 8
// speedup vs baseline: 1.0321x; 1.0321x over previous
#include <cuda_runtime.h>
#include <cuda_bf16.h>
#include <cstdint>
#include <math.h>

#define NROWS 32768
#define FDIM  128
#define KDIM  64
#define MNBR  32
#define NTILES (NROWS/4)

// Scratch (allocation-free rule: __device__ globals)
__device__ float g_xi [NROWS*FDIM];
__device__ float g_xjp[NROWS*FDIM];
__device__ float g_m0 [NROWS*FDIM];
__device__ float g_m1 [NROWS*FDIM];
__device__ __align__(16) __nv_bfloat16 g_wbH[7*16384];
__device__ __align__(16) __nv_bfloat16 g_wbL[7*16384];
__device__ __align__(16) __nv_bfloat16 g_tH[NROWS*FDIM];   // bufA: raw t splits
__device__ __align__(16) __nv_bfloat16 g_tL[NROWS*FDIM];
__device__ __align__(16) __nv_bfloat16 g_sH[NROWS*FDIM];   // bufB: ssp-activation splits
__device__ __align__(16) __nv_bfloat16 g_sL[NROWS*FDIM];

__device__ __forceinline__ float sspf(float a) {
    return fmaxf(a, 0.0f) + log1pf(expf(-fabsf(a))) - 0.69314718055994530942f;
}

// ---------------- mma.sync helpers ----------------
__device__ __forceinline__ uint32_t s2u(const void* p) {
    uint32_t a;
    asm("{ .reg .u64 t; cvta.to.shared.u64 t, %1; cvt.u32.u64 %0, t; }" : "=r"(a) : "l"(p));
    return a;
}

#define LDM_X4(r, addr) \
    asm volatile("ldmatrix.sync.aligned.m8n8.x4.shared.b16 {%0,%1,%2,%3}, [%4];" \
        : "=r"((r)[0]), "=r"((r)[1]), "=r"((r)[2]), "=r"((r)[3]) : "r"(addr))

#define MMA_BF16(d, a, b0, b1) \
    asm volatile("mma.sync.aligned.m16n8k16.row.col.f32.bf16.bf16.f32 " \
        "{%0,%1,%2,%3}, {%4,%5,%6,%7}, {%8,%9}, {%0,%1,%2,%3};" \
        : "+f"((d)[0]), "+f"((d)[1]), "+f"((d)[2]), "+f"((d)[3]) \
        : "r"((a)[0]), "r"((a)[1]), "r"((a)[2]), "r"((a)[3]), "r"(b0), "r"(b1))

__device__ __forceinline__ void bf16_split4(float4 v, __nv_bfloat16* H, __nv_bfloat16* L) {
    __nv_bfloat16 h0 = __float2bfloat16(v.x), h1 = __float2bfloat16(v.y),
                  h2 = __float2bfloat16(v.z), h3 = __float2bfloat16(v.w);
    *(__nv_bfloat162*)(H)     = __nv_bfloat162(h0, h1);
    *(__nv_bfloat162*)(H + 2) = __nv_bfloat162(h2, h3);
    *(__nv_bfloat162*)(L)     = __nv_bfloat162(__float2bfloat16(v.x - __bfloat162float(h0)),
                                               __float2bfloat16(v.y - __bfloat162float(h1)));
    *(__nv_bfloat162*)(L + 2) = __nv_bfloat162(__float2bfloat16(v.z - __bfloat162float(h2)),
                                               __float2bfloat16(v.w - __bfloat162float(h3)));
}

// ---------------- weight pre-split: 7 matrices of 128x128 ----------------
__global__ void __launch_bounds__(256) prep_w(
    const float* __restrict__ wi, const float* __restrict__ wj,
    const float* __restrict__ rw1, const float* __restrict__ rw2,
    const float* __restrict__ wd,
    __nv_bfloat16* __restrict__ WH, __nv_bfloat16* __restrict__ WL)
{
    int idx = blockIdx.x * 256 + threadIdx.x;   // float4 idx, 7*4096 total
    int mat = idx >> 12, off = idx & 4095;
    const float* src;
    switch (mat) {
        case 0: src = wi; break;
        case 1: src = wj; break;
        case 2: src = rw1; break;
        case 3: src = rw2; break;
        case 4: src = rw1 + 16384; break;
        case 5: src = rw2 + 16384; break;
        default: src = wd; break;
    }
    float4 v = ((const float4*)src)[off];
    size_t d = (size_t)mat * 16384 + (size_t)off * 4;
    bf16_split4(v, WH + d, WL + d);
}

// =================================================================================
// Tensor-core row GEMM, pre-split weights. 256 threads, 64x128 tile, 2 CTAs/SM.
// AMODE 0: A = split(ssp(fp32 in));  AMODE 1: A = pre-split H/L (pure copy).
// Epilogue: o = slab + b (+ addp [*u]); optional fp32 out; optional H/L split of [ssp] o.
// =================================================================================
#define TG_WH    0u
#define TG_WL    34816u
#define TG_U     69632u
#define TG_AH    TG_U
#define TG_AL    (TG_U + 17408u)
#define TG_BIAS  104448u
#define TG_MUL   104960u
#define TG_TOTAL 105472u
#define TG_SLABS 132

template<int AMODE, bool ADD, bool MULVEC, bool OUTF32, bool OUTSPLIT, bool OSSP>
__global__ __launch_bounds__(256, 2) void tg2(
    const void* __restrict__ aSrc, const __nv_bfloat16* __restrict__ aLsrc,
    const __nv_bfloat16* __restrict__ wHsrc, const __nv_bfloat16* __restrict__ wLsrc,
    const float* __restrict__ bias, const float* __restrict__ addp,
    const float* __restrict__ mulv, float* __restrict__ outf,
    __nv_bfloat16* __restrict__ oH, __nv_bfloat16* __restrict__ oL)
{
    extern __shared__ char smem[];
    __nv_bfloat16* AH = (__nv_bfloat16*)(smem + TG_AH);
    __nv_bfloat16* AL = (__nv_bfloat16*)(smem + TG_AL);
    float* slab = (float*)(smem + TG_U);
    float* b_sm = (float*)(smem + TG_BIAS);
    float* u_sm = (float*)(smem + TG_MUL);

    const int tid = threadIdx.x;
    const int wid = tid >> 5, lid = tid & 31;
    const uint32_t sb = s2u(smem);

    // W: pure copy of pre-split bf16 (2048 uint4 per buffer)
    #pragma unroll
    for (int i = 0; i < 8; i++) {
        int idx = tid + 256 * i;
        int row = idx >> 4, c8 = idx & 15;
        *(uint4*)(smem + TG_WH + row * 272 + c8 * 16) = ((const uint4*)wHsrc)[idx];
        *(uint4*)(smem + TG_WL + row * 272 + c8 * 16) = ((const uint4*)wLsrc)[idx];
    }
    if (tid < 128) {
        b_sm[tid] = bias[tid];
        u_sm[tid] = MULVEC ? mulv[tid] : 0.0f;
    }

    const int r0 = blockIdx.x * 64;

    if (AMODE == 0) {
        // fp32 -> ssp -> split (only for x-GEMMs; overlaps MMA-phase of co-resident CTA)
        #pragma unroll
        for (int i = 0; i < 8; i++) {
            int fidx = tid + 256 * i;        // float4 over 2048
            float4 v = ((const float4*)((const float*)aSrc + (size_t)r0 * FDIM))[fidx];
            v.x = sspf(v.x); v.y = sspf(v.y); v.z = sspf(v.z); v.w = sspf(v.w);
            int row = fidx >> 5, c = (fidx & 31) * 4;
            bf16_split4(v, AH + row * 136 + c, AL + row * 136 + c);
        }
    } else {
        // pre-split pure copy (1024 uint4 per buffer)
        const uint4* aH4 = (const uint4*)((const __nv_bfloat16*)aSrc + (size_t)r0 * FDIM);
        const uint4* aL4 = (const uint4*)(aLsrc + (size_t)r0 * FDIM);
        #pragma unroll
        for (int i = 0; i < 4; i++) {
            int idx = tid + 256 * i;
            int row = idx >> 4, c8 = idx & 15;
            *(uint4*)(smem + TG_AH + row * 272 + c8 * 16) = aH4[idx];
            *(uint4*)(smem + TG_AL + row * 272 + c8 * 16) = aL4[idx];
        }
    }
    __syncthreads();

    const uint32_t aL_off = (((lid & 7) + (lid & 8)) * 136 + ((lid & 16) ? 8 : 0)) * 2;
    const uint32_t bL_off = (((lid & 7) + ((lid & 16) >> 1)) * 136 + ((lid & 8) ? 8 : 0)) * 2;
    const int wr = wid & 1, wc = wid >> 1;

    float acc[2][4][4];
    #pragma unroll
    for (int mt = 0; mt < 2; mt++)
        #pragma unroll
        for (int nb = 0; nb < 4; nb++)
            #pragma unroll
            for (int c = 0; c < 4; c++) acc[mt][nb][c] = 0.f;

    #pragma unroll
    for (int kk = 0; kk < 8; kk++) {
        const uint32_t kb = (uint32_t)kk * 32;
        uint32_t ah[2][4], al[2][4], bh[2][4], bl[2][4];
        #pragma unroll
        for (int mt = 0; mt < 2; mt++) {
            uint32_t ro = (uint32_t)(32*wr + 16*mt) * 272 + kb;
            LDM_X4(ah[mt], sb + TG_AH + aL_off + ro);
            LDM_X4(al[mt], sb + TG_AL + aL_off + ro);
        }
        #pragma unroll
        for (int np = 0; np < 2; np++) {
            uint32_t no = (uint32_t)(32*wc + 16*np) * 272 + kb;
            LDM_X4(bh[np], sb + TG_WH + bL_off + no);
            LDM_X4(bl[np], sb + TG_WL + bL_off + no);
        }
        #pragma unroll
        for (int mt = 0; mt < 2; mt++)
            #pragma unroll
            for (int np = 0; np < 2; np++) {
                MMA_BF16(acc[mt][2*np],   ah[mt], bh[np][0], bh[np][1]);
                MMA_BF16(acc[mt][2*np+1], ah[mt], bh[np][2], bh[np][3]);
                MMA_BF16(acc[mt][2*np],   ah[mt], bl[np][0], bl[np][1]);
                MMA_BF16(acc[mt][2*np+1], ah[mt], bl[np][2], bl[np][3]);
                MMA_BF16(acc[mt][2*np],   al[mt], bh[np][0], bh[np][1]);
                MMA_BF16(acc[mt][2*np+1], al[mt], bh[np][2], bh[np][3]);
            }
    }
    __syncthreads();   // A reads done -> union becomes slab

    {
        const int g = lid >> 2, t = lid & 3;
        #pragma unroll
        for (int mt = 0; mt < 2; mt++)
            #pragma unroll
            for (int nb = 0; nb < 4; nb++) {
                int e = 32*wr + 16*mt + g;
                int c = 32*wc + 8*nb + 2*t;
                *(float2*)&slab[e * TG_SLABS + c] = make_float2(acc[mt][nb][0], acc[mt][nb][1]);
                *(float2*)&slab[(e+8) * TG_SLABS + c] = make_float2(acc[mt][nb][2], acc[mt][nb][3]);
            }
    }
    __syncthreads();

    #pragma unroll
    for (int i = 0; i < 32; i++) {
        int idx = tid + 256 * i;
        int row = idx >> 7, col = idx & 127;
        size_t gpos = (size_t)(r0 + row) * FDIM + col;
        float o = slab[row * TG_SLABS + col] + b_sm[col];
        if (ADD) {
            float av = addp[gpos];
            o += MULVEC ? av * u_sm[col] : av;
        }
        if (OUTF32) outf[gpos] = o;
        if (OUTSPLIT) {
            float s = OSSP ? sspf(o) : o;
            __nv_bfloat16 h = __float2bfloat16(s);
            oH[gpos] = h;
            oL[gpos] = __float2bfloat16(s - __bfloat162float(h));
        }
    }
}

// =================================================================================
// Fused edge-filter GEMM + gather + attention (R5 512-thread version, validated @432)
// + epilogue now also writes split(ssp(m0)) for the residual chain.
// =================================================================================
#define OFF_BH   0u
#define OFF_BL   18432u
#define OFF_U    36864u
#define OFF_AH   OFF_U
#define OFF_AL   (OFF_U + 18432u)
#define OFF_XI   104448u
#define OFF_PART 106496u
#define OFF_ATT  114688u
#define OFF_JIDX 115200u
#define SM_TOTAL 115712u
#define SLAB_STRIDE 132

__global__ void __launch_bounds__(512, 1) attn_mma(
    const float* __restrict__ rbf, const int* __restrict__ idxj,
    const float* __restrict__ k2f, const float* __restrict__ xi,
    const float* __restrict__ xjp, float* __restrict__ mout,
    __nv_bfloat16* __restrict__ oH, __nv_bfloat16* __restrict__ oL)
{
    extern __shared__ char smem[];
    __nv_bfloat16* AH = (__nv_bfloat16*)(smem + OFF_AH);
    __nv_bfloat16* AL = (__nv_bfloat16*)(smem + OFF_AL);
    __nv_bfloat16* BH = (__nv_bfloat16*)(smem + OFF_BH);
    __nv_bfloat16* BL = (__nv_bfloat16*)(smem + OFF_BL);
    float* slab   = (float*)(smem + OFF_U);
    float* xi_sm  = (float*)(smem + OFF_XI);
    float* part   = (float*)(smem + OFF_PART);
    float* att_sm = (float*)(smem + OFF_ATT);
    int*   jidx   = (int*)  (smem + OFF_JIDX);

    const int tid = threadIdx.x;
    const int wid = tid >> 5, lid = tid & 31;
    const uint32_t sb = s2u(smem);

    #pragma unroll
    for (int i = 0; i < 4; i++) {
        int fidx = tid + 512 * i;
        float4 v = ((const float4*)k2f)[fidx];
        int row = fidx >> 4, c = (fidx & 15) * 4;
        bf16_split4(v, BH + row*72 + c, BL + row*72 + c);
    }
    __syncthreads();

    const uint32_t aL = ((((lid & 7) + (lid & 8)) * 72) + ((lid & 16) ? 8 : 0)) * 2;
    const uint32_t bL = ((((lid & 7) + ((lid & 16) >> 1)) * 72) + ((lid & 8) ? 8 : 0)) * 2;
    const int wr = wid & 3, wc = wid >> 2;

    const int f  = tid & 127;
    const int q  = f >> 5;
    const int e0 = tid >> 7;

    for (int tile = blockIdx.x; tile < NTILES; tile += gridDim.x) {
        const int n0 = tile * 4;

        const float4* rp = (const float4*)(rbf + (size_t)tile * 8192);
        #pragma unroll
        for (int i = 0; i < 4; i++) {
            int fidx = tid + 512 * i;
            float4 v = rp[fidx];
            int row = fidx >> 4, c = (fidx & 15) * 4;
            bf16_split4(v, AH + row*72 + c, AL + row*72 + c);
        }
        if (tid < 128) jidx[tid] = idxj[tile * 128 + tid];
        if (tid < 512) xi_sm[tid] = xi[(size_t)n0 * FDIM + tid];
        __syncthreads();

        float acc[2][4][4];
        #pragma unroll
        for (int mt = 0; mt < 2; mt++)
            #pragma unroll
            for (int nb = 0; nb < 4; nb++)
                #pragma unroll
                for (int c = 0; c < 4; c++) acc[mt][nb][c] = 0.f;

        #pragma unroll
        for (int kk = 0; kk < 4; kk++) {
            const uint32_t kb = (uint32_t)kk * 32;
            uint32_t ah[2][4], al[2][4], bh[2][4], bl[2][4];
            #pragma unroll
            for (int mt = 0; mt < 2; mt++) {
                uint32_t ro = (uint32_t)(32*wr + 16*mt) * 144 + kb;
                LDM_X4(ah[mt], sb + OFF_AH + aL + ro);
                LDM_X4(al[mt], sb + OFF_AL + aL + ro);
            }
            #pragma unroll
            for (int np = 0; np < 2; np++) {
                uint32_t no = (uint32_t)(32*wc + 16*np) * 144 + kb;
                LDM_X4(bh[np], sb + OFF_BH + bL + no);
                LDM_X4(bl[np], sb + OFF_BL + bL + no);
            }
            #pragma unroll
            for (int mt = 0; mt < 2; mt++)
                #pragma unroll
                for (int np = 0; np < 2; np++) {
                    MMA_BF16(acc[mt][2*np],   ah[mt], bh[np][0], bh[np][1]);
                    MMA_BF16(acc[mt][2*np+1], ah[mt], bh[np][2], bh[np][3]);
                    MMA_BF16(acc[mt][2*np],   ah[mt], bl[np][0], bl[np][1]);
                    MMA_BF16(acc[mt][2*np+1], ah[mt], bl[np][2], bl[np][3]);
                    MMA_BF16(acc[mt][2*np],   al[mt], bh[np][0], bh[np][1]);
                    MMA_BF16(acc[mt][2*np+1], al[mt], bh[np][2], bh[np][3]);
                }
        }
        __syncthreads();

        {
            const int g = lid >> 2, t = lid & 3;
            #pragma unroll
            for (int mt = 0; mt < 2; mt++)
                #pragma unroll
                for (int nb = 0; nb < 4; nb++) {
                    int e = 32*wr + 16*mt + g;
                    int c = 32*wc + 8*nb + 2*t;
                    *(float2*)&slab[e * SLAB_STRIDE + c] =
                        make_float2(acc[mt][nb][0], acc[mt][nb][1]);
                    *(float2*)&slab[(e + 8) * SLAB_STRIDE + c] =
                        make_float2(acc[mt][nb][2], acc[mt][nb][3]);
                }
        }
        __syncthreads();

        float xp[32];
        #pragma unroll
        for (int i = 0; i < 32; i++)
            xp[i] = xjp[(size_t)jidx[4*i + e0] * FDIM + f];

        float lacc[4] = {0.f, 0.f, 0.f, 0.f};
        #pragma unroll
        for (int i = 0; i < 32; i++) {
            const int e = 4*i + e0;
            const int a = i >> 3;
            const int m = e & 31;
            float p = slab[e * SLAB_STRIDE + f] * xp[i];
            xp[i] = p;
            lacc[a] += xi_sm[a * FDIM + 4*m + q] * p;
        }
        #pragma unroll
        for (int a = 0; a < 4; a++)
            part[wid * 128 + a * 32 + lid] = lacc[a];
        __syncthreads();

        if (wid < 4) {
            float lg = 0.f;
            #pragma unroll
            for (int w2 = 0; w2 < 16; w2++) lg += part[w2 * 128 + wid * 32 + lid];
            float mx = lg;
            #pragma unroll
            for (int o = 16; o; o >>= 1) mx = fmaxf(mx, __shfl_xor_sync(0xffffffffu, mx, o));
            float ex = expf(lg - mx);
            float smv = ex;
            #pragma unroll
            for (int o = 16; o; o >>= 1) smv += __shfl_xor_sync(0xffffffffu, smv, o);
            att_sm[wid * 32 + lid] = ex / smv;
        }
        __syncthreads();

        float pacc[4] = {0.f, 0.f, 0.f, 0.f};
        #pragma unroll
        for (int i = 0; i < 32; i++) {
            const int e = 4*i + e0;
            const int a = i >> 3;
            const int m = e & 31;
            pacc[a] += att_sm[a * 32 + m] * xp[i];
        }
        #pragma unroll
        for (int a = 0; a < 4; a++)
            part[e0 * 512 + a * 128 + f] = pacc[a];
        __syncthreads();

        {
            size_t gpos = (size_t)n0 * FDIM + tid;
            float mv = xi_sm[tid]
                + part[tid] + part[512 + tid] + part[1024 + tid] + part[1536 + tid];
            mout[gpos] = mv;
            float s = sspf(mv);
            __nv_bfloat16 h = __float2bfloat16(s);
            oH[gpos] = h;
            oL[gpos] = __float2bfloat16(s - __bfloat162float(h));
        }
        __syncthreads();
    }
}

extern "C" void kernel_launch(void* const* d_in, const int* in_sizes, int n_in,
                              void* d_out, int out_size)
{
    const float* x    = (const float*)d_in[0];
    const float* rbf  = (const float*)d_in[1];
    const int*   idxj = (const int*)  d_in[3];
    const float* k2f  = (const float*)d_in[4];
    const float* wi   = (const float*)d_in[5];
    const float* bi   = (const float*)d_in[6];
    const float* wj   = (const float*)d_in[7];
    const float* bj   = (const float*)d_in[8];
    const float* rw1  = (const float*)d_in[9];
    const float* rb1  = (const float*)d_in[10];
    const float* rw2  = (const float*)d_in[11];
    const float* rb2  = (const float*)d_in[12];
    const float* wd   = (const float*)d_in[13];
    const float* bd   = (const float*)d_in[14];
    const float* u    = (const float*)d_in[15];
    float* out = (float*)d_out;

    float *xi_p, *xjp_p, *m0_p, *m1_p;
    __nv_bfloat16 *wbH, *wbL, *tH, *tL, *sH, *sL;
    cudaGetSymbolAddress((void**)&xi_p,  g_xi);
    cudaGetSymbolAddress((void**)&xjp_p, g_xjp);
    cudaGetSymbolAddress((void**)&m0_p,  g_m0);
    cudaGetSymbolAddress((void**)&m1_p,  g_m1);
    cudaGetSymbolAddress((void**)&wbH,   g_wbH);
    cudaGetSymbolAddress((void**)&wbL,   g_wbL);
    cudaGetSymbolAddress((void**)&tH,    g_tH);
    cudaGetSymbolAddress((void**)&tL,    g_tL);
    cudaGetSymbolAddress((void**)&sH,    g_sH);
    cudaGetSymbolAddress((void**)&sL,    g_sL);

    static int nsm = 0;
    if (nsm == 0) {
        cudaDeviceGetAttribute(&nsm, cudaDevAttrMultiProcessorCount, 0);
        if (nsm <= 0) nsm = 148;
        cudaFuncSetAttribute(attn_mma, cudaFuncAttributeMaxDynamicSharedMemorySize, SM_TOTAL);
        cudaFuncSetAttribute(tg2<0,false,false,true,false,false>, cudaFuncAttributeMaxDynamicSharedMemorySize, TG_TOTAL);
        cudaFuncSetAttribute(tg2<1,false,false,false,true,false>, cudaFuncAttributeMaxDynamicSharedMemorySize, TG_TOTAL);
        cudaFuncSetAttribute(tg2<1,true,false,true,true,true>,    cudaFuncAttributeMaxDynamicSharedMemorySize, TG_TOTAL);
        cudaFuncSetAttribute(tg2<1,true,false,false,true,true>,   cudaFuncAttributeMaxDynamicSharedMemorySize, TG_TOTAL);
        cudaFuncSetAttribute(tg2<1,true,true,true,false,false>,   cudaFuncAttributeMaxDynamicSharedMemorySize, TG_TOTAL);
    }

    const int TG_GRID = NROWS / 64;   // 512

    // weight pre-split (slots: 0=wi 1=wj 2=rw1[0] 3=rw2[0] 4=rw1[1] 5=rw2[1] 6=wd)
    prep_w<<<112, 256>>>(wi, wj, rw1, rw2, wd, wbH, wbL);

    // xi = ssp(x)@wi.T+bi ; xjp = ssp(x)@wj.T+bj
    tg2<0,false,false,true,false,false><<<TG_GRID, 256, TG_TOTAL>>>(
        x, nullptr, wbH, wbL, bi, nullptr, nullptr, xi_p, nullptr, nullptr);
    tg2<0,false,false,true,false,false><<<TG_GRID, 256, TG_TOTAL>>>(
        x, nullptr, wbH + 16384, wbL + 16384, bj, nullptr, nullptr, xjp_p, nullptr, nullptr);

    // m0 = attention; also emits split(ssp(m0)) -> bufB
    attn_mma<<<nsm, 512, SM_TOTAL>>>(rbf, idxj, k2f, xi_p, xjp_p, m0_p, sH, sL);

    // res block 0:  t = ssp(m0)@w1+b1 (split only) ; m1 = m0 + t@w2+b2 (+ split ssp(m1))
    tg2<1,false,false,false,true,false><<<TG_GRID, 256, TG_TOTAL>>>(
        sH, sL, wbH + 2*16384, wbL + 2*16384, rb1, nullptr, nullptr, nullptr, tH, tL);
    tg2<1,true,false,true,true,true><<<TG_GRID, 256, TG_TOTAL>>>(
        tH, tL, wbH + 3*16384, wbL + 3*16384, rb2, m0_p, nullptr, m1_p, sH, sL);

    // res block 1:  t = ssp(m1)@w1'+b1' ; split(ssp(m2)) only (m2 fp32 never needed)
    tg2<1,false,false,false,true,false><<<TG_GRID, 256, TG_TOTAL>>>(
        sH, sL, wbH + 4*16384, wbL + 4*16384, rb1 + FDIM, nullptr, nullptr, nullptr, tH, tL);
    tg2<1,true,false,false,true,true><<<TG_GRID, 256, TG_TOTAL>>>(
        tH, tL, wbH + 5*16384, wbL + 5*16384, rb2 + FDIM, m1_p, nullptr, nullptr, sH, sL);

    // out = u*x + ssp(m2)@wd+bd
    tg2<1,true,true,true,false,false><<<TG_GRID, 256, TG_TOTAL>>>(
        sH, sL, wbH + 6*16384, wbL + 6*16384, bd, x, u, out, nullptr, nullptr);
}

// round 9
// speedup vs baseline: 1.1278x; 1.0928x over previous
#include <cuda_runtime.h>
#include <cuda_bf16.h>
#include <cstdint>
#include <math.h>

#define NROWS 32768
#define FDIM  128
#define KDIM  64
#define MNBR  32
#define NTILES (NROWS/4)

// Scratch (allocation-free rule: __device__ globals)
__device__ float g_xi [NROWS*FDIM];
__device__ float g_xjp[NROWS*FDIM];
__device__ float g_m0 [NROWS*FDIM];
__device__ float g_m1 [NROWS*FDIM];
__device__ __align__(16) __nv_bfloat16 g_wbH[7*16384];
__device__ __align__(16) __nv_bfloat16 g_wbL[7*16384];
__device__ __align__(16) __nv_bfloat16 g_tH[NROWS*FDIM];
__device__ __align__(16) __nv_bfloat16 g_tL[NROWS*FDIM];
__device__ __align__(16) __nv_bfloat16 g_sH[NROWS*FDIM];
__device__ __align__(16) __nv_bfloat16 g_sL[NROWS*FDIM];

__device__ __forceinline__ float sspf(float a) {
    return fmaxf(a, 0.0f) + log1pf(expf(-fabsf(a))) - 0.69314718055994530942f;
}

// ---------------- mma.sync / cp.async helpers ----------------
__device__ __forceinline__ uint32_t s2u(const void* p) {
    uint32_t a;
    asm("{ .reg .u64 t; cvta.to.shared.u64 t, %1; cvt.u32.u64 %0, t; }" : "=r"(a) : "l"(p));
    return a;
}

#define LDM_X4(r, addr) \
    asm volatile("ldmatrix.sync.aligned.m8n8.x4.shared.b16 {%0,%1,%2,%3}, [%4];" \
        : "=r"((r)[0]), "=r"((r)[1]), "=r"((r)[2]), "=r"((r)[3]) : "r"(addr))

#define MMA_BF16(d, a, b0, b1) \
    asm volatile("mma.sync.aligned.m16n8k16.row.col.f32.bf16.bf16.f32 " \
        "{%0,%1,%2,%3}, {%4,%5,%6,%7}, {%8,%9}, {%0,%1,%2,%3};" \
        : "+f"((d)[0]), "+f"((d)[1]), "+f"((d)[2]), "+f"((d)[3]) \
        : "r"((a)[0]), "r"((a)[1]), "r"((a)[2]), "r"((a)[3]), "r"(b0), "r"(b1))

#define CP16(dst, src) \
    asm volatile("cp.async.cg.shared.global [%0], [%1], 16;" :: "r"(dst), "l"(src) : "memory")
#define CP_COMMIT() asm volatile("cp.async.commit_group;" ::: "memory")
#define CP_WAIT0()  asm volatile("cp.async.wait_group 0;" ::: "memory")

__device__ __forceinline__ void bf16_split4(float4 v, __nv_bfloat16* H, __nv_bfloat16* L) {
    __nv_bfloat16 h0 = __float2bfloat16(v.x), h1 = __float2bfloat16(v.y),
                  h2 = __float2bfloat16(v.z), h3 = __float2bfloat16(v.w);
    *(__nv_bfloat162*)(H)     = __nv_bfloat162(h0, h1);
    *(__nv_bfloat162*)(H + 2) = __nv_bfloat162(h2, h3);
    *(__nv_bfloat162*)(L)     = __nv_bfloat162(__float2bfloat16(v.x - __bfloat162float(h0)),
                                               __float2bfloat16(v.y - __bfloat162float(h1)));
    *(__nv_bfloat162*)(L + 2) = __nv_bfloat162(__float2bfloat16(v.z - __bfloat162float(h2)),
                                               __float2bfloat16(v.w - __bfloat162float(h3)));
}

// ---------------- weight pre-split: 7 matrices of 128x128 ----------------
__global__ void __launch_bounds__(256) prep_w(
    const float* __restrict__ wi, const float* __restrict__ wj,
    const float* __restrict__ rw1, const float* __restrict__ rw2,
    const float* __restrict__ wd,
    __nv_bfloat16* __restrict__ WH, __nv_bfloat16* __restrict__ WL)
{
    int idx = blockIdx.x * 256 + threadIdx.x;
    int mat = idx >> 12, off = idx & 4095;
    const float* src;
    switch (mat) {
        case 0: src = wi; break;
        case 1: src = wj; break;
        case 2: src = rw1; break;
        case 3: src = rw2; break;
        case 4: src = rw1 + 16384; break;
        case 5: src = rw2 + 16384; break;
        default: src = wd; break;
    }
    float4 v = ((const float4*)src)[off];
    size_t d = (size_t)mat * 16384 + (size_t)off * 4;
    bf16_split4(v, WH + d, WL + d);
}

// =================================================================================
// Tensor-core row GEMM, pre-split weights (validated R8). 256 thr, 64x128, 2 CTA/SM.
// =================================================================================
#define TG_WH    0u
#define TG_WL    34816u
#define TG_U     69632u
#define TG_AH    TG_U
#define TG_AL    (TG_U + 17408u)
#define TG_BIAS  104448u
#define TG_MUL   104960u
#define TG_TOTAL 105472u
#define TG_SLABS 132

template<int AMODE, bool ADD, bool MULVEC, bool OUTF32, bool OUTSPLIT, bool OSSP>
__global__ __launch_bounds__(256, 2) void tg2(
    const void* __restrict__ aSrc, const __nv_bfloat16* __restrict__ aLsrc,
    const __nv_bfloat16* __restrict__ wHsrc, const __nv_bfloat16* __restrict__ wLsrc,
    const float* __restrict__ bias, const float* __restrict__ addp,
    const float* __restrict__ mulv, float* __restrict__ outf,
    __nv_bfloat16* __restrict__ oH, __nv_bfloat16* __restrict__ oL)
{
    extern __shared__ char smem[];
    __nv_bfloat16* AH = (__nv_bfloat16*)(smem + TG_AH);
    __nv_bfloat16* AL = (__nv_bfloat16*)(smem + TG_AL);
    float* slab = (float*)(smem + TG_U);
    float* b_sm = (float*)(smem + TG_BIAS);
    float* u_sm = (float*)(smem + TG_MUL);

    const int tid = threadIdx.x;
    const int wid = tid >> 5, lid = tid & 31;
    const uint32_t sb = s2u(smem);

    #pragma unroll
    for (int i = 0; i < 8; i++) {
        int idx = tid + 256 * i;
        int row = idx >> 4, c8 = idx & 15;
        *(uint4*)(smem + TG_WH + row * 272 + c8 * 16) = ((const uint4*)wHsrc)[idx];
        *(uint4*)(smem + TG_WL + row * 272 + c8 * 16) = ((const uint4*)wLsrc)[idx];
    }
    if (tid < 128) {
        b_sm[tid] = bias[tid];
        u_sm[tid] = MULVEC ? mulv[tid] : 0.0f;
    }

    const int r0 = blockIdx.x * 64;

    if (AMODE == 0) {
        #pragma unroll
        for (int i = 0; i < 8; i++) {
            int fidx = tid + 256 * i;
            float4 v = ((const float4*)((const float*)aSrc + (size_t)r0 * FDIM))[fidx];
            v.x = sspf(v.x); v.y = sspf(v.y); v.z = sspf(v.z); v.w = sspf(v.w);
            int row = fidx >> 5, c = (fidx & 31) * 4;
            bf16_split4(v, AH + row * 136 + c, AL + row * 136 + c);
        }
    } else {
        const uint4* aH4 = (const uint4*)((const __nv_bfloat16*)aSrc + (size_t)r0 * FDIM);
        const uint4* aL4 = (const uint4*)(aLsrc + (size_t)r0 * FDIM);
        #pragma unroll
        for (int i = 0; i < 4; i++) {
            int idx = tid + 256 * i;
            int row = idx >> 4, c8 = idx & 15;
            *(uint4*)(smem + TG_AH + row * 272 + c8 * 16) = aH4[idx];
            *(uint4*)(smem + TG_AL + row * 272 + c8 * 16) = aL4[idx];
        }
    }
    __syncthreads();

    const uint32_t aL_off = (((lid & 7) + (lid & 8)) * 136 + ((lid & 16) ? 8 : 0)) * 2;
    const uint32_t bL_off = (((lid & 7) + ((lid & 16) >> 1)) * 136 + ((lid & 8) ? 8 : 0)) * 2;
    const int wr = wid & 1, wc = wid >> 1;

    float acc[2][4][4];
    #pragma unroll
    for (int mt = 0; mt < 2; mt++)
        #pragma unroll
        for (int nb = 0; nb < 4; nb++)
            #pragma unroll
            for (int c = 0; c < 4; c++) acc[mt][nb][c] = 0.f;

    #pragma unroll
    for (int kk = 0; kk < 8; kk++) {
        const uint32_t kb = (uint32_t)kk * 32;
        uint32_t ah[2][4], al[2][4], bh[2][4], bl[2][4];
        #pragma unroll
        for (int mt = 0; mt < 2; mt++) {
            uint32_t ro = (uint32_t)(32*wr + 16*mt) * 272 + kb;
            LDM_X4(ah[mt], sb + TG_AH + aL_off + ro);
            LDM_X4(al[mt], sb + TG_AL + aL_off + ro);
        }
        #pragma unroll
        for (int np = 0; np < 2; np++) {
            uint32_t no = (uint32_t)(32*wc + 16*np) * 272 + kb;
            LDM_X4(bh[np], sb + TG_WH + bL_off + no);
            LDM_X4(bl[np], sb + TG_WL + bL_off + no);
        }
        #pragma unroll
        for (int mt = 0; mt < 2; mt++)
            #pragma unroll
            for (int np = 0; np < 2; np++) {
                MMA_BF16(acc[mt][2*np],   ah[mt], bh[np][0], bh[np][1]);
                MMA_BF16(acc[mt][2*np+1], ah[mt], bh[np][2], bh[np][3]);
                MMA_BF16(acc[mt][2*np],   ah[mt], bl[np][0], bl[np][1]);
                MMA_BF16(acc[mt][2*np+1], ah[mt], bl[np][2], bl[np][3]);
                MMA_BF16(acc[mt][2*np],   al[mt], bh[np][0], bh[np][1]);
                MMA_BF16(acc[mt][2*np+1], al[mt], bh[np][2], bh[np][3]);
            }
    }
    __syncthreads();

    {
        const int g = lid >> 2, t = lid & 3;
        #pragma unroll
        for (int mt = 0; mt < 2; mt++)
            #pragma unroll
            for (int nb = 0; nb < 4; nb++) {
                int e = 32*wr + 16*mt + g;
                int c = 32*wc + 8*nb + 2*t;
                *(float2*)&slab[e * TG_SLABS + c] = make_float2(acc[mt][nb][0], acc[mt][nb][1]);
                *(float2*)&slab[(e+8) * TG_SLABS + c] = make_float2(acc[mt][nb][2], acc[mt][nb][3]);
            }
    }
    __syncthreads();

    #pragma unroll
    for (int i = 0; i < 32; i++) {
        int idx = tid + 256 * i;
        int row = idx >> 7, col = idx & 127;
        size_t gpos = (size_t)(r0 + row) * FDIM + col;
        float o = slab[row * TG_SLABS + col] + b_sm[col];
        if (ADD) {
            float av = addp[gpos];
            o += MULVEC ? av * u_sm[col] : av;
        }
        if (OUTF32) outf[gpos] = o;
        if (OUTSPLIT) {
            float s = OSSP ? sspf(o) : o;
            __nv_bfloat16 h = __float2bfloat16(s);
            oH[gpos] = h;
            oL[gpos] = __float2bfloat16(s - __bfloat162float(h));
        }
    }
}

// =================================================================================
// Fused edge-filter GEMM + gather + attention — software-pipelined with cp.async.
// =================================================================================
#define OFF_BH   0u
#define OFF_BL   18432u
#define OFF_U    36864u          // AH/AL (36864) | slab 128x132 fp32 (67584)
#define OFF_AH   OFF_U
#define OFF_AL   (OFF_U + 18432u)
#define OFF_XPB  104448u         // gathered xjp rows [128][128] fp32 = 65536
#define OFF_STG  169984u         // rbf raw staging 32768
#define OFF_XI2  202752u         // 2 x 2048 (double-buffered xi)
#define OFF_PART 206848u         // float[2048]
#define OFF_ATT  215040u         // float[128]
#define OFF_JB   215552u         // 2 x 512 (double-buffered jidx)
#define SM_TOTAL 216576u
#define SLAB_STRIDE 132

__global__ void __launch_bounds__(512, 1) attn_mma(
    const float* __restrict__ rbf, const int* __restrict__ idxj,
    const float* __restrict__ k2f, const float* __restrict__ xi,
    const float* __restrict__ xjp, float* __restrict__ mout,
    __nv_bfloat16* __restrict__ oH, __nv_bfloat16* __restrict__ oL)
{
    extern __shared__ char smem[];
    __nv_bfloat16* AH = (__nv_bfloat16*)(smem + OFF_AH);
    __nv_bfloat16* AL = (__nv_bfloat16*)(smem + OFF_AL);
    __nv_bfloat16* BH = (__nv_bfloat16*)(smem + OFF_BH);
    __nv_bfloat16* BL = (__nv_bfloat16*)(smem + OFF_BL);
    float* slab   = (float*)(smem + OFF_U);
    float* xpb    = (float*)(smem + OFF_XPB);
    float* part   = (float*)(smem + OFF_PART);
    float* att_sm = (float*)(smem + OFF_ATT);

    const int tid = threadIdx.x;
    const int wid = tid >> 5, lid = tid & 31;
    const uint32_t sb = s2u(smem);

    // B = k2f, hi/lo split, once
    #pragma unroll
    for (int i = 0; i < 4; i++) {
        int fidx = tid + 512 * i;
        float4 v = ((const float4*)k2f)[fidx];
        int row = fidx >> 4, c = (fidx & 15) * 4;
        bf16_split4(v, BH + row*72 + c, BL + row*72 + c);
    }

    const uint32_t aL = ((((lid & 7) + (lid & 8)) * 72) + ((lid & 16) ? 8 : 0)) * 2;
    const uint32_t bL = ((((lid & 7) + ((lid & 16) >> 1)) * 72) + ((lid & 8) ? 8 : 0)) * 2;
    const int wr = wid & 3, wc = wid >> 2;
    const int f  = tid & 127;
    const int q  = f >> 5;
    const int e0 = tid >> 7;
    const int stride = gridDim.x;

    // ---- stage issue: rbf raw -> STG (per-thread chunks), xi -> XI2[sel], jidx -> JB[sel]
    auto stage = [&](int tile, int sel) {
        const char* rsrc = (const char*)(rbf + (size_t)tile * 8192);
        #pragma unroll
        for (int i = 0; i < 4; i++) {
            uint32_t o = (uint32_t)(tid + 512 * i) * 16u;
            CP16(sb + OFF_STG + o, rsrc + o);
        }
        if (tid < 128)
            CP16(sb + OFF_XI2 + (uint32_t)sel * 2048u + tid * 16u,
                 (const char*)(xi + (size_t)tile * 512) + tid * 16);
        if (tid < 32)
            CP16(sb + OFF_JB + (uint32_t)sel * 512u + tid * 16u,
                 (const char*)(idxj + tile * 128) + tid * 16);
    };
    // ---- gather issue: xjp rows per JB[sel] -> XPB (warp = 8 rows, lane = 16B)
    auto gather = [&](int sel) {
        const int* jb = (const int*)(smem + OFF_JB + sel * 512);
        #pragma unroll
        for (int r = 0; r < 8; r++) {
            int e = wid * 8 + r;
            int j = jb[e];
            CP16(sb + OFF_XPB + (uint32_t)e * 512u + lid * 16u,
                 (const char*)(xjp + (size_t)j * FDIM) + lid * 16);
        }
    };

    // prime pipeline for first tile
    int cur = 0;
    stage(blockIdx.x, 0);
    CP_COMMIT();
    CP_WAIT0();
    __syncthreads();      // staging + B visible
    gather(0);
    CP_COMMIT();

    for (int tile = blockIdx.x; tile < NTILES; tile += stride) {
        const int n0 = tile * 4;
        const int nxt = tile + stride;
        const bool has = nxt < NTILES;

        // A split from smem staging (each thread re-reads exactly what it will restage)
        #pragma unroll
        for (int i = 0; i < 4; i++) {
            int fidx = tid + 512 * i;
            float4 v = *(const float4*)(smem + OFF_STG + (uint32_t)fidx * 16u);
            int row = fidx >> 4, c = (fidx & 15) * 4;
            bf16_split4(v, AH + row*72 + c, AL + row*72 + c);
        }
        if (has) stage(nxt, cur ^ 1);
        CP_COMMIT();
        __syncthreads();

        // MMA 128x128x64, bf16 hi/lo 3-pass
        float acc[2][4][4];
        #pragma unroll
        for (int mt = 0; mt < 2; mt++)
            #pragma unroll
            for (int nb = 0; nb < 4; nb++)
                #pragma unroll
                for (int c = 0; c < 4; c++) acc[mt][nb][c] = 0.f;

        #pragma unroll
        for (int kk = 0; kk < 4; kk++) {
            const uint32_t kb = (uint32_t)kk * 32;
            uint32_t ah[2][4], al[2][4], bh[2][4], bl[2][4];
            #pragma unroll
            for (int mt = 0; mt < 2; mt++) {
                uint32_t ro = (uint32_t)(32*wr + 16*mt) * 144 + kb;
                LDM_X4(ah[mt], sb + OFF_AH + aL + ro);
                LDM_X4(al[mt], sb + OFF_AL + aL + ro);
            }
            #pragma unroll
            for (int np = 0; np < 2; np++) {
                uint32_t no = (uint32_t)(32*wc + 16*np) * 144 + kb;
                LDM_X4(bh[np], sb + OFF_BH + bL + no);
                LDM_X4(bl[np], sb + OFF_BL + bL + no);
            }
            #pragma unroll
            for (int mt = 0; mt < 2; mt++)
                #pragma unroll
                for (int np = 0; np < 2; np++) {
                    MMA_BF16(acc[mt][2*np],   ah[mt], bh[np][0], bh[np][1]);
                    MMA_BF16(acc[mt][2*np+1], ah[mt], bh[np][2], bh[np][3]);
                    MMA_BF16(acc[mt][2*np],   ah[mt], bl[np][0], bl[np][1]);
                    MMA_BF16(acc[mt][2*np+1], ah[mt], bl[np][2], bl[np][3]);
                    MMA_BF16(acc[mt][2*np],   al[mt], bh[np][0], bh[np][1]);
                    MMA_BF16(acc[mt][2*np+1], al[mt], bh[np][2], bh[np][3]);
                }
        }
        __syncthreads();   // A dead -> slab

        {
            const int g = lid >> 2, t = lid & 3;
            #pragma unroll
            for (int mt = 0; mt < 2; mt++)
                #pragma unroll
                for (int nb = 0; nb < 4; nb++) {
                    int e = 32*wr + 16*mt + g;
                    int c = 32*wc + 8*nb + 2*t;
                    *(float2*)&slab[e * SLAB_STRIDE + c] =
                        make_float2(acc[mt][nb][0], acc[mt][nb][1]);
                    *(float2*)&slab[(e + 8) * SLAB_STRIDE + c] =
                        make_float2(acc[mt][nb][2], acc[mt][nb][3]);
                }
        }
        CP_WAIT0();        // gathered xpb (and next-tile staging) landed
        __syncthreads();

        const float* xi_c = (const float*)(smem + OFF_XI2 + (uint32_t)cur * 2048u);

        // product + logit partials (faithful flat reshape)
        float xp[32];
        float lacc[4] = {0.f, 0.f, 0.f, 0.f};
        #pragma unroll
        for (int i = 0; i < 32; i++) {
            const int e = 4*i + e0;
            const int a = i >> 3;
            const int m = e & 31;
            float p = slab[e * SLAB_STRIDE + f] * xpb[e * FDIM + f];
            xp[i] = p;
            lacc[a] += xi_c[a * FDIM + 4*m + q] * p;
        }
        #pragma unroll
        for (int a = 0; a < 4; a++)
            part[wid * 128 + a * 32 + lid] = lacc[a];
        __syncthreads();

        if (wid < 4) {
            float lg = 0.f;
            #pragma unroll
            for (int w2 = 0; w2 < 16; w2++) lg += part[w2 * 128 + wid * 32 + lid];
            float mx = lg;
            #pragma unroll
            for (int o = 16; o; o >>= 1) mx = fmaxf(mx, __shfl_xor_sync(0xffffffffu, mx, o));
            float ex = expf(lg - mx);
            float smv = ex;
            #pragma unroll
            for (int o = 16; o; o >>= 1) smv += __shfl_xor_sync(0xffffffffu, smv, o);
            att_sm[wid * 32 + lid] = ex / smv;
        }
        __syncthreads();

        float pacc[4] = {0.f, 0.f, 0.f, 0.f};
        #pragma unroll
        for (int i = 0; i < 32; i++) {
            const int e = 4*i + e0;
            const int a = i >> 3;
            const int m = e & 31;
            pacc[a] += att_sm[a * 32 + m] * xp[i];
        }
        #pragma unroll
        for (int a = 0; a < 4; a++)
            part[e0 * 512 + a * 128 + f] = pacc[a];
        __syncthreads();

        {
            size_t gpos = (size_t)n0 * FDIM + tid;
            float mv = xi_c[tid]
                + part[tid] + part[512 + tid] + part[1024 + tid] + part[1536 + tid];
            mout[gpos] = mv;
            float s = sspf(mv);
            __nv_bfloat16 h = __float2bfloat16(s);
            oH[gpos] = h;
            oL[gpos] = __float2bfloat16(s - __bfloat162float(h));
        }

        if (has) gather(cur ^ 1);   // prefetch next tile's xjp rows into xpb
        CP_COMMIT();
        __syncthreads();
        cur ^= 1;
    }
}

extern "C" void kernel_launch(void* const* d_in, const int* in_sizes, int n_in,
                              void* d_out, int out_size)
{
    const float* x    = (const float*)d_in[0];
    const float* rbf  = (const float*)d_in[1];
    const int*   idxj = (const int*)  d_in[3];
    const float* k2f  = (const float*)d_in[4];
    const float* wi   = (const float*)d_in[5];
    const float* bi   = (const float*)d_in[6];
    const float* wj   = (const float*)d_in[7];
    const float* bj   = (const float*)d_in[8];
    const float* rw1  = (const float*)d_in[9];
    const float* rb1  = (const float*)d_in[10];
    const float* rw2  = (const float*)d_in[11];
    const float* rb2  = (const float*)d_in[12];
    const float* wd   = (const float*)d_in[13];
    const float* bd   = (const float*)d_in[14];
    const float* u    = (const float*)d_in[15];
    float* out = (float*)d_out;

    float *xi_p, *xjp_p, *m0_p, *m1_p;
    __nv_bfloat16 *wbH, *wbL, *tH, *tL, *sH, *sL;
    cudaGetSymbolAddress((void**)&xi_p,  g_xi);
    cudaGetSymbolAddress((void**)&xjp_p, g_xjp);
    cudaGetSymbolAddress((void**)&m0_p,  g_m0);
    cudaGetSymbolAddress((void**)&m1_p,  g_m1);
    cudaGetSymbolAddress((void**)&wbH,   g_wbH);
    cudaGetSymbolAddress((void**)&wbL,   g_wbL);
    cudaGetSymbolAddress((void**)&tH,    g_tH);
    cudaGetSymbolAddress((void**)&tL,    g_tL);
    cudaGetSymbolAddress((void**)&sH,    g_sH);
    cudaGetSymbolAddress((void**)&sL,    g_sL);

    static int nsm = 0;
    if (nsm == 0) {
        cudaDeviceGetAttribute(&nsm, cudaDevAttrMultiProcessorCount, 0);
        if (nsm <= 0) nsm = 148;
        cudaFuncSetAttribute(attn_mma, cudaFuncAttributeMaxDynamicSharedMemorySize, SM_TOTAL);
        cudaFuncSetAttribute(tg2<0,false,false,true,false,false>, cudaFuncAttributeMaxDynamicSharedMemorySize, TG_TOTAL);
        cudaFuncSetAttribute(tg2<1,false,false,false,true,false>, cudaFuncAttributeMaxDynamicSharedMemorySize, TG_TOTAL);
        cudaFuncSetAttribute(tg2<1,true,false,true,true,true>,    cudaFuncAttributeMaxDynamicSharedMemorySize, TG_TOTAL);
        cudaFuncSetAttribute(tg2<1,true,false,false,true,true>,   cudaFuncAttributeMaxDynamicSharedMemorySize, TG_TOTAL);
        cudaFuncSetAttribute(tg2<1,true,true,true,false,false>,   cudaFuncAttributeMaxDynamicSharedMemorySize, TG_TOTAL);
    }

    const int TG_GRID = NROWS / 64;   // 512

    prep_w<<<112, 256>>>(wi, wj, rw1, rw2, wd, wbH, wbL);

    tg2<0,false,false,true,false,false><<<TG_GRID, 256, TG_TOTAL>>>(
        x, nullptr, wbH, wbL, bi, nullptr, nullptr, xi_p, nullptr, nullptr);
    tg2<0,false,false,true,false,false><<<TG_GRID, 256, TG_TOTAL>>>(
        x, nullptr, wbH + 16384, wbL + 16384, bj, nullptr, nullptr, xjp_p, nullptr, nullptr);

    attn_mma<<<nsm, 512, SM_TOTAL>>>(rbf, idxj, k2f, xi_p, xjp_p, m0_p, sH, sL);

    tg2<1,false,false,false,true,false><<<TG_GRID, 256, TG_TOTAL>>>(
        sH, sL, wbH + 2*16384, wbL + 2*16384, rb1, nullptr, nullptr, nullptr, tH, tL);
    tg2<1,true,false,true,true,true><<<TG_GRID, 256, TG_TOTAL>>>(
        tH, tL, wbH + 3*16384, wbL + 3*16384, rb2, m0_p, nullptr, m1_p, sH, sL);
    tg2<1,false,false,false,true,false><<<TG_GRID, 256, TG_TOTAL>>>(
        sH, sL, wbH + 4*16384, wbL + 4*16384, rb1 + FDIM, nullptr, nullptr, nullptr, tH, tL);
    tg2<1,true,false,false,true,true><<<TG_GRID, 256, TG_TOTAL>>>(
        tH, tL, wbH + 5*16384, wbL + 5*16384, rb2 + FDIM, m1_p, nullptr, nullptr, sH, sL);
    tg2<1,true,true,true,false,false><<<TG_GRID, 256, TG_TOTAL>>>(
        sH, sL, wbH + 6*16384, wbL + 6*16384, bd, x, u, out, nullptr, nullptr);
}

// round 10
// speedup vs baseline: 1.2368x; 1.0966x over previous
#include <cuda_runtime.h>
#include <cuda_bf16.h>
#include <cuda_fp16.h>
#include <cstdint>
#include <math.h>

#define NROWS 32768
#define FDIM  128
#define KDIM  64
#define MNBR  32
#define NTILES (NROWS/4)

// Scratch (allocation-free rule: __device__ globals)
__device__ float g_xi [NROWS*FDIM];
__device__ float g_xjp[NROWS*FDIM];
__device__ float g_m0 [NROWS*FDIM];
__device__ float g_m1 [NROWS*FDIM];
__device__ __align__(16) __nv_bfloat16 g_wbH[7*16384];
__device__ __align__(16) __nv_bfloat16 g_wbL[7*16384];
__device__ __align__(16) __nv_bfloat16 g_tH[NROWS*FDIM];
__device__ __align__(16) __nv_bfloat16 g_tL[NROWS*FDIM];
__device__ __align__(16) __nv_bfloat16 g_sH[NROWS*FDIM];
__device__ __align__(16) __nv_bfloat16 g_sL[NROWS*FDIM];

__device__ __forceinline__ float sspf(float a) {
    return fmaxf(a, 0.0f) + log1pf(expf(-fabsf(a))) - 0.69314718055994530942f;
}

// ---------------- mma.sync / cp.async helpers ----------------
__device__ __forceinline__ uint32_t s2u(const void* p) {
    uint32_t a;
    asm("{ .reg .u64 t; cvta.to.shared.u64 t, %1; cvt.u32.u64 %0, t; }" : "=r"(a) : "l"(p));
    return a;
}

#define LDM_X4(r, addr) \
    asm volatile("ldmatrix.sync.aligned.m8n8.x4.shared.b16 {%0,%1,%2,%3}, [%4];" \
        : "=r"((r)[0]), "=r"((r)[1]), "=r"((r)[2]), "=r"((r)[3]) : "r"(addr))

#define MMA_BF16(d, a, b0, b1) \
    asm volatile("mma.sync.aligned.m16n8k16.row.col.f32.bf16.bf16.f32 " \
        "{%0,%1,%2,%3}, {%4,%5,%6,%7}, {%8,%9}, {%0,%1,%2,%3};" \
        : "+f"((d)[0]), "+f"((d)[1]), "+f"((d)[2]), "+f"((d)[3]) \
        : "r"((a)[0]), "r"((a)[1]), "r"((a)[2]), "r"((a)[3]), "r"(b0), "r"(b1))

#define MMA_F16(d, a, b0, b1) \
    asm volatile("mma.sync.aligned.m16n8k16.row.col.f32.f16.f16.f32 " \
        "{%0,%1,%2,%3}, {%4,%5,%6,%7}, {%8,%9}, {%0,%1,%2,%3};" \
        : "+f"((d)[0]), "+f"((d)[1]), "+f"((d)[2]), "+f"((d)[3]) \
        : "r"((a)[0]), "r"((a)[1]), "r"((a)[2]), "r"((a)[3]), "r"(b0), "r"(b1))

#define CP16(dst, src) \
    asm volatile("cp.async.cg.shared.global [%0], [%1], 16;" :: "r"(dst), "l"(src) : "memory")
#define CP_COMMIT() asm volatile("cp.async.commit_group;" ::: "memory")
#define CP_WAIT0()  asm volatile("cp.async.wait_group 0;" ::: "memory")

__device__ __forceinline__ void bf16_split4(float4 v, __nv_bfloat16* H, __nv_bfloat16* L) {
    __nv_bfloat16 h0 = __float2bfloat16(v.x), h1 = __float2bfloat16(v.y),
                  h2 = __float2bfloat16(v.z), h3 = __float2bfloat16(v.w);
    *(__nv_bfloat162*)(H)     = __nv_bfloat162(h0, h1);
    *(__nv_bfloat162*)(H + 2) = __nv_bfloat162(h2, h3);
    *(__nv_bfloat162*)(L)     = __nv_bfloat162(__float2bfloat16(v.x - __bfloat162float(h0)),
                                               __float2bfloat16(v.y - __bfloat162float(h1)));
    *(__nv_bfloat162*)(L + 2) = __nv_bfloat162(__float2bfloat16(v.z - __bfloat162float(h2)),
                                               __float2bfloat16(v.w - __bfloat162float(h3)));
}

__device__ __forceinline__ void f16_split4(float4 v, __half* H, __half* L) {
    __half h0 = __float2half_rn(v.x), h1 = __float2half_rn(v.y),
           h2 = __float2half_rn(v.z), h3 = __float2half_rn(v.w);
    *(__half2*)(H)     = __half2(h0, h1);
    *(__half2*)(H + 2) = __half2(h2, h3);
    *(__half2*)(L)     = __half2(__float2half_rn(v.x - __half2float(h0)),
                                 __float2half_rn(v.y - __half2float(h1)));
    *(__half2*)(L + 2) = __half2(__float2half_rn(v.z - __half2float(h2)),
                                 __float2half_rn(v.w - __half2float(h3)));
}

// ---------------- weight pre-split: 7 matrices of 128x128 (bf16 hi/lo) ----------------
__global__ void __launch_bounds__(256) prep_w(
    const float* __restrict__ wi, const float* __restrict__ wj,
    const float* __restrict__ rw1, const float* __restrict__ rw2,
    const float* __restrict__ wd,
    __nv_bfloat16* __restrict__ WH, __nv_bfloat16* __restrict__ WL)
{
    int idx = blockIdx.x * 256 + threadIdx.x;
    int mat = idx >> 12, off = idx & 4095;
    const float* src;
    switch (mat) {
        case 0: src = wi; break;
        case 1: src = wj; break;
        case 2: src = rw1; break;
        case 3: src = rw2; break;
        case 4: src = rw1 + 16384; break;
        case 5: src = rw2 + 16384; break;
        default: src = wd; break;
    }
    float4 v = ((const float4*)src)[off];
    size_t d = (size_t)mat * 16384 + (size_t)off * 4;
    bf16_split4(v, WH + d, WL + d);
}

// =================================================================================
// Tensor-core row GEMM, pre-split bf16 weights (validated). 256 thr, 64x128, 2 CTA/SM.
// =================================================================================
#define TG_WH    0u
#define TG_WL    34816u
#define TG_U     69632u
#define TG_AH    TG_U
#define TG_AL    (TG_U + 17408u)
#define TG_BIAS  104448u
#define TG_MUL   104960u
#define TG_TOTAL 105472u
#define TG_SLABS 132

template<int AMODE, bool ADD, bool MULVEC, bool OUTF32, bool OUTSPLIT, bool OSSP>
__global__ __launch_bounds__(256, 2) void tg2(
    const void* __restrict__ aSrc, const __nv_bfloat16* __restrict__ aLsrc,
    const __nv_bfloat16* __restrict__ wHsrc, const __nv_bfloat16* __restrict__ wLsrc,
    const float* __restrict__ bias, const float* __restrict__ addp,
    const float* __restrict__ mulv, float* __restrict__ outf,
    __nv_bfloat16* __restrict__ oH, __nv_bfloat16* __restrict__ oL)
{
    extern __shared__ char smem[];
    __nv_bfloat16* AH = (__nv_bfloat16*)(smem + TG_AH);
    __nv_bfloat16* AL = (__nv_bfloat16*)(smem + TG_AL);
    float* slab = (float*)(smem + TG_U);
    float* b_sm = (float*)(smem + TG_BIAS);
    float* u_sm = (float*)(smem + TG_MUL);

    const int tid = threadIdx.x;
    const int wid = tid >> 5, lid = tid & 31;
    const uint32_t sb = s2u(smem);

    #pragma unroll
    for (int i = 0; i < 8; i++) {
        int idx = tid + 256 * i;
        int row = idx >> 4, c8 = idx & 15;
        *(uint4*)(smem + TG_WH + row * 272 + c8 * 16) = ((const uint4*)wHsrc)[idx];
        *(uint4*)(smem + TG_WL + row * 272 + c8 * 16) = ((const uint4*)wLsrc)[idx];
    }
    if (tid < 128) {
        b_sm[tid] = bias[tid];
        u_sm[tid] = MULVEC ? mulv[tid] : 0.0f;
    }

    const int r0 = blockIdx.x * 64;

    if (AMODE == 0) {
        #pragma unroll
        for (int i = 0; i < 8; i++) {
            int fidx = tid + 256 * i;
            float4 v = ((const float4*)((const float*)aSrc + (size_t)r0 * FDIM))[fidx];
            v.x = sspf(v.x); v.y = sspf(v.y); v.z = sspf(v.z); v.w = sspf(v.w);
            int row = fidx >> 5, c = (fidx & 31) * 4;
            bf16_split4(v, AH + row * 136 + c, AL + row * 136 + c);
        }
    } else {
        const uint4* aH4 = (const uint4*)((const __nv_bfloat16*)aSrc + (size_t)r0 * FDIM);
        const uint4* aL4 = (const uint4*)(aLsrc + (size_t)r0 * FDIM);
        #pragma unroll
        for (int i = 0; i < 4; i++) {
            int idx = tid + 256 * i;
            int row = idx >> 4, c8 = idx & 15;
            *(uint4*)(smem + TG_AH + row * 272 + c8 * 16) = aH4[idx];
            *(uint4*)(smem + TG_AL + row * 272 + c8 * 16) = aL4[idx];
        }
    }
    __syncthreads();

    const uint32_t aL_off = (((lid & 7) + (lid & 8)) * 136 + ((lid & 16) ? 8 : 0)) * 2;
    const uint32_t bL_off = (((lid & 7) + ((lid & 16) >> 1)) * 136 + ((lid & 8) ? 8 : 0)) * 2;
    const int wr = wid & 1, wc = wid >> 1;

    float acc[2][4][4];
    #pragma unroll
    for (int mt = 0; mt < 2; mt++)
        #pragma unroll
        for (int nb = 0; nb < 4; nb++)
            #pragma unroll
            for (int c = 0; c < 4; c++) acc[mt][nb][c] = 0.f;

    #pragma unroll
    for (int kk = 0; kk < 8; kk++) {
        const uint32_t kb = (uint32_t)kk * 32;
        uint32_t ah[2][4], al[2][4], bh[2][4], bl[2][4];
        #pragma unroll
        for (int mt = 0; mt < 2; mt++) {
            uint32_t ro = (uint32_t)(32*wr + 16*mt) * 272 + kb;
            LDM_X4(ah[mt], sb + TG_AH + aL_off + ro);
            LDM_X4(al[mt], sb + TG_AL + aL_off + ro);
        }
        #pragma unroll
        for (int np = 0; np < 2; np++) {
            uint32_t no = (uint32_t)(32*wc + 16*np) * 272 + kb;
            LDM_X4(bh[np], sb + TG_WH + bL_off + no);
            LDM_X4(bl[np], sb + TG_WL + bL_off + no);
        }
        #pragma unroll
        for (int mt = 0; mt < 2; mt++)
            #pragma unroll
            for (int np = 0; np < 2; np++) {
                MMA_BF16(acc[mt][2*np],   ah[mt], bh[np][0], bh[np][1]);
                MMA_BF16(acc[mt][2*np+1], ah[mt], bh[np][2], bh[np][3]);
                MMA_BF16(acc[mt][2*np],   ah[mt], bl[np][0], bl[np][1]);
                MMA_BF16(acc[mt][2*np+1], ah[mt], bl[np][2], bl[np][3]);
                MMA_BF16(acc[mt][2*np],   al[mt], bh[np][0], bh[np][1]);
                MMA_BF16(acc[mt][2*np+1], al[mt], bh[np][2], bh[np][3]);
            }
    }
    __syncthreads();

    {
        const int g = lid >> 2, t = lid & 3;
        #pragma unroll
        for (int mt = 0; mt < 2; mt++)
            #pragma unroll
            for (int nb = 0; nb < 4; nb++) {
                int e = 32*wr + 16*mt + g;
                int c = 32*wc + 8*nb + 2*t;
                *(float2*)&slab[e * TG_SLABS + c] = make_float2(acc[mt][nb][0], acc[mt][nb][1]);
                *(float2*)&slab[(e+8) * TG_SLABS + c] = make_float2(acc[mt][nb][2], acc[mt][nb][3]);
            }
    }
    __syncthreads();

    #pragma unroll
    for (int i = 0; i < 32; i++) {
        int idx = tid + 256 * i;
        int row = idx >> 7, col = idx & 127;
        size_t gpos = (size_t)(r0 + row) * FDIM + col;
        float o = slab[row * TG_SLABS + col] + b_sm[col];
        if (ADD) {
            float av = addp[gpos];
            o += MULVEC ? av * u_sm[col] : av;
        }
        if (OUTF32) outf[gpos] = o;
        if (OUTSPLIT) {
            float s = OSSP ? sspf(o) : o;
            __nv_bfloat16 h = __float2bfloat16(s);
            oH[gpos] = h;
            oL[gpos] = __float2bfloat16(s - __bfloat162float(h));
        }
    }
}

// =================================================================================
// Fused edge-filter GEMM + gather + attention — cp.async pipelined, fp16 2-pass MMA.
// A = rbf single fp16; B = k2f hi/lo fp16 (Bh+Bl == B), so D error = A quantization.
// =================================================================================
#define OFF_BH   0u
#define OFF_BL   18432u
#define OFF_U    36864u          // AH fp16 (18432) | slab 128x132 fp32 (67584) union
#define OFF_AH   OFF_U
#define OFF_XPB  104448u         // gathered xjp rows [128][128] fp32 = 65536
#define OFF_STG  169984u         // rbf raw staging 32768
#define OFF_XI2  202752u         // 2 x 2048 (double-buffered xi)
#define OFF_PART 206848u         // float[2048]
#define OFF_ATT  215040u         // float[128]
#define OFF_JB   215552u         // 2 x 512 (double-buffered jidx)
#define SM_TOTAL 216576u
#define SLAB_STRIDE 132

__global__ void __launch_bounds__(512, 1) attn_mma(
    const float* __restrict__ rbf, const int* __restrict__ idxj,
    const float* __restrict__ k2f, const float* __restrict__ xi,
    const float* __restrict__ xjp, float* __restrict__ mout,
    __nv_bfloat16* __restrict__ oH, __nv_bfloat16* __restrict__ oL)
{
    extern __shared__ char smem[];
    __half* AH = (__half*)(smem + OFF_AH);
    __half* BH = (__half*)(smem + OFF_BH);
    __half* BL = (__half*)(smem + OFF_BL);
    float* slab   = (float*)(smem + OFF_U);
    float* xpb    = (float*)(smem + OFF_XPB);
    float* part   = (float*)(smem + OFF_PART);
    float* att_sm = (float*)(smem + OFF_ATT);

    const int tid = threadIdx.x;
    const int wid = tid >> 5, lid = tid & 31;
    const uint32_t sb = s2u(smem);

    // B = k2f, fp16 hi/lo split, once
    #pragma unroll
    for (int i = 0; i < 4; i++) {
        int fidx = tid + 512 * i;
        float4 v = ((const float4*)k2f)[fidx];
        int row = fidx >> 4, c = (fidx & 15) * 4;
        f16_split4(v, BH + row*72 + c, BL + row*72 + c);
    }

    const uint32_t aL = ((((lid & 7) + (lid & 8)) * 72) + ((lid & 16) ? 8 : 0)) * 2;
    const uint32_t bL = ((((lid & 7) + ((lid & 16) >> 1)) * 72) + ((lid & 8) ? 8 : 0)) * 2;
    const int wr = wid & 3, wc = wid >> 2;
    const int f  = tid & 127;
    const int q  = f >> 5;
    const int e0 = tid >> 7;
    const int stride = gridDim.x;

    auto stage = [&](int tile, int sel) {
        const char* rsrc = (const char*)(rbf + (size_t)tile * 8192);
        #pragma unroll
        for (int i = 0; i < 4; i++) {
            uint32_t o = (uint32_t)(tid + 512 * i) * 16u;
            CP16(sb + OFF_STG + o, rsrc + o);
        }
        if (tid < 128)
            CP16(sb + OFF_XI2 + (uint32_t)sel * 2048u + tid * 16u,
                 (const char*)(xi + (size_t)tile * 512) + tid * 16);
        if (tid < 32)
            CP16(sb + OFF_JB + (uint32_t)sel * 512u + tid * 16u,
                 (const char*)(idxj + tile * 128) + tid * 16);
    };
    auto gather = [&](int sel) {
        const int* jb = (const int*)(smem + OFF_JB + sel * 512);
        #pragma unroll
        for (int r = 0; r < 8; r++) {
            int e = wid * 8 + r;
            int j = jb[e];
            CP16(sb + OFF_XPB + (uint32_t)e * 512u + lid * 16u,
                 (const char*)(xjp + (size_t)j * FDIM) + lid * 16);
        }
    };

    int cur = 0;
    stage(blockIdx.x, 0);
    CP_COMMIT();
    CP_WAIT0();
    __syncthreads();
    gather(0);
    CP_COMMIT();

    for (int tile = blockIdx.x; tile < NTILES; tile += stride) {
        const int n0 = tile * 4;
        const int nxt = tile + stride;
        const bool has = nxt < NTILES;

        // A: fp32 staging -> single fp16 (no lo buffer)
        #pragma unroll
        for (int i = 0; i < 4; i++) {
            int fidx = tid + 512 * i;
            float4 v = *(const float4*)(smem + OFF_STG + (uint32_t)fidx * 16u);
            int row = fidx >> 4, c = (fidx & 15) * 4;
            __half* dst = AH + row*72 + c;
            *(__half2*)(dst)     = __floats2half2_rn(v.x, v.y);
            *(__half2*)(dst + 2) = __floats2half2_rn(v.z, v.w);
        }
        if (has) stage(nxt, cur ^ 1);
        CP_COMMIT();
        __syncthreads();

        // MMA 128x128x64: D = A*(Bh+Bl), fp16 2-pass
        float acc[2][4][4];
        #pragma unroll
        for (int mt = 0; mt < 2; mt++)
            #pragma unroll
            for (int nb = 0; nb < 4; nb++)
                #pragma unroll
                for (int c = 0; c < 4; c++) acc[mt][nb][c] = 0.f;

        #pragma unroll
        for (int kk = 0; kk < 4; kk++) {
            const uint32_t kb = (uint32_t)kk * 32;
            uint32_t ah[2][4], bh[2][4], bl[2][4];
            #pragma unroll
            for (int mt = 0; mt < 2; mt++) {
                uint32_t ro = (uint32_t)(32*wr + 16*mt) * 144 + kb;
                LDM_X4(ah[mt], sb + OFF_AH + aL + ro);
            }
            #pragma unroll
            for (int np = 0; np < 2; np++) {
                uint32_t no = (uint32_t)(32*wc + 16*np) * 144 + kb;
                LDM_X4(bh[np], sb + OFF_BH + bL + no);
                LDM_X4(bl[np], sb + OFF_BL + bL + no);
            }
            #pragma unroll
            for (int mt = 0; mt < 2; mt++)
                #pragma unroll
                for (int np = 0; np < 2; np++) {
                    MMA_F16(acc[mt][2*np],   ah[mt], bh[np][0], bh[np][1]);
                    MMA_F16(acc[mt][2*np+1], ah[mt], bh[np][2], bh[np][3]);
                    MMA_F16(acc[mt][2*np],   ah[mt], bl[np][0], bl[np][1]);
                    MMA_F16(acc[mt][2*np+1], ah[mt], bl[np][2], bl[np][3]);
                }
        }
        __syncthreads();   // A dead -> slab

        {
            const int g = lid >> 2, t = lid & 3;
            #pragma unroll
            for (int mt = 0; mt < 2; mt++)
                #pragma unroll
                for (int nb = 0; nb < 4; nb++) {
                    int e = 32*wr + 16*mt + g;
                    int c = 32*wc + 8*nb + 2*t;
                    *(float2*)&slab[e * SLAB_STRIDE + c] =
                        make_float2(acc[mt][nb][0], acc[mt][nb][1]);
                    *(float2*)&slab[(e + 8) * SLAB_STRIDE + c] =
                        make_float2(acc[mt][nb][2], acc[mt][nb][3]);
                }
        }
        CP_WAIT0();
        __syncthreads();

        const float* xi_c = (const float*)(smem + OFF_XI2 + (uint32_t)cur * 2048u);

        float xp[32];
        float lacc[4] = {0.f, 0.f, 0.f, 0.f};
        #pragma unroll
        for (int i = 0; i < 32; i++) {
            const int e = 4*i + e0;
            const int a = i >> 3;
            const int m = e & 31;
            float p = slab[e * SLAB_STRIDE + f] * xpb[e * FDIM + f];
            xp[i] = p;
            lacc[a] += xi_c[a * FDIM + 4*m + q] * p;
        }
        #pragma unroll
        for (int a = 0; a < 4; a++)
            part[wid * 128 + a * 32 + lid] = lacc[a];
        __syncthreads();

        if (wid < 4) {
            float lg = 0.f;
            #pragma unroll
            for (int w2 = 0; w2 < 16; w2++) lg += part[w2 * 128 + wid * 32 + lid];
            float mx = lg;
            #pragma unroll
            for (int o = 16; o; o >>= 1) mx = fmaxf(mx, __shfl_xor_sync(0xffffffffu, mx, o));
            float ex = expf(lg - mx);
            float smv = ex;
            #pragma unroll
            for (int o = 16; o; o >>= 1) smv += __shfl_xor_sync(0xffffffffu, smv, o);
            att_sm[wid * 32 + lid] = ex / smv;
        }
        __syncthreads();

        float pacc[4] = {0.f, 0.f, 0.f, 0.f};
        #pragma unroll
        for (int i = 0; i < 32; i++) {
            const int e = 4*i + e0;
            const int a = i >> 3;
            const int m = e & 31;
            pacc[a] += att_sm[a * 32 + m] * xp[i];
        }
        #pragma unroll
        for (int a = 0; a < 4; a++)
            part[e0 * 512 + a * 128 + f] = pacc[a];
        __syncthreads();

        {
            size_t gpos = (size_t)n0 * FDIM + tid;
            float mv = xi_c[tid]
                + part[tid] + part[512 + tid] + part[1024 + tid] + part[1536 + tid];
            mout[gpos] = mv;
            float s = sspf(mv);
            __nv_bfloat16 h = __float2bfloat16(s);
            oH[gpos] = h;
            oL[gpos] = __float2bfloat16(s - __bfloat162float(h));
        }

        if (has) gather(cur ^ 1);
        CP_COMMIT();
        __syncthreads();
        cur ^= 1;
    }
}

extern "C" void kernel_launch(void* const* d_in, const int* in_sizes, int n_in,
                              void* d_out, int out_size)
{
    const float* x    = (const float*)d_in[0];
    const float* rbf  = (const float*)d_in[1];
    const int*   idxj = (const int*)  d_in[3];
    const float* k2f  = (const float*)d_in[4];
    const float* wi   = (const float*)d_in[5];
    const float* bi   = (const float*)d_in[6];
    const float* wj   = (const float*)d_in[7];
    const float* bj   = (const float*)d_in[8];
    const float* rw1  = (const float*)d_in[9];
    const float* rb1  = (const float*)d_in[10];
    const float* rw2  = (const float*)d_in[11];
    const float* rb2  = (const float*)d_in[12];
    const float* wd   = (const float*)d_in[13];
    const float* bd   = (const float*)d_in[14];
    const float* u    = (const float*)d_in[15];
    float* out = (float*)d_out;

    float *xi_p, *xjp_p, *m0_p, *m1_p;
    __nv_bfloat16 *wbH, *wbL, *tH, *tL, *sH, *sL;
    cudaGetSymbolAddress((void**)&xi_p,  g_xi);
    cudaGetSymbolAddress((void**)&xjp_p, g_xjp);
    cudaGetSymbolAddress((void**)&m0_p,  g_m0);
    cudaGetSymbolAddress((void**)&m1_p,  g_m1);
    cudaGetSymbolAddress((void**)&wbH,   g_wbH);
    cudaGetSymbolAddress((void**)&wbL,   g_wbL);
    cudaGetSymbolAddress((void**)&tH,    g_tH);
    cudaGetSymbolAddress((void**)&tL,    g_tL);
    cudaGetSymbolAddress((void**)&sH,    g_sH);
    cudaGetSymbolAddress((void**)&sL,    g_sL);

    static int nsm = 0;
    if (nsm == 0) {
        cudaDeviceGetAttribute(&nsm, cudaDevAttrMultiProcessorCount, 0);
        if (nsm <= 0) nsm = 148;
        cudaFuncSetAttribute(attn_mma, cudaFuncAttributeMaxDynamicSharedMemorySize, SM_TOTAL);
        cudaFuncSetAttribute(tg2<0,false,false,true,false,false>, cudaFuncAttributeMaxDynamicSharedMemorySize, TG_TOTAL);
        cudaFuncSetAttribute(tg2<1,false,false,false,true,false>, cudaFuncAttributeMaxDynamicSharedMemorySize, TG_TOTAL);
        cudaFuncSetAttribute(tg2<1,true,false,true,true,true>,    cudaFuncAttributeMaxDynamicSharedMemorySize, TG_TOTAL);
        cudaFuncSetAttribute(tg2<1,true,false,false,true,true>,   cudaFuncAttributeMaxDynamicSharedMemorySize, TG_TOTAL);
        cudaFuncSetAttribute(tg2<1,true,true,true,false,false>,   cudaFuncAttributeMaxDynamicSharedMemorySize, TG_TOTAL);
    }

    const int TG_GRID = NROWS / 64;   // 512

    prep_w<<<112, 256>>>(wi, wj, rw1, rw2, wd, wbH, wbL);

    tg2<0,false,false,true,false,false><<<TG_GRID, 256, TG_TOTAL>>>(
        x, nullptr, wbH, wbL, bi, nullptr, nullptr, xi_p, nullptr, nullptr);
    tg2<0,false,false,true,false,false><<<TG_GRID, 256, TG_TOTAL>>>(
        x, nullptr, wbH + 16384, wbL + 16384, bj, nullptr, nullptr, xjp_p, nullptr, nullptr);

    attn_mma<<<nsm, 512, SM_TOTAL>>>(rbf, idxj, k2f, xi_p, xjp_p, m0_p, sH, sL);

    tg2<1,false,false,false,true,false><<<TG_GRID, 256, TG_TOTAL>>>(
        sH, sL, wbH + 2*16384, wbL + 2*16384, rb1, nullptr, nullptr, nullptr, tH, tL);
    tg2<1,true,false,true,true,true><<<TG_GRID, 256, TG_TOTAL>>>(
        tH, tL, wbH + 3*16384, wbL + 3*16384, rb2, m0_p, nullptr, m1_p, sH, sL);
    tg2<1,false,false,false,true,false><<<TG_GRID, 256, TG_TOTAL>>>(
        sH, sL, wbH + 4*16384, wbL + 4*16384, rb1 + FDIM, nullptr, nullptr, nullptr, tH, tL);
    tg2<1,true,false,false,true,true><<<TG_GRID, 256, TG_TOTAL>>>(
        tH, tL, wbH + 5*16384, wbL + 5*16384, rb2 + FDIM, m1_p, nullptr, nullptr, sH, sL);
    tg2<1,true,true,true,false,false><<<TG_GRID, 256, TG_TOTAL>>>(
        sH, sL, wbH + 6*16384, wbL + 6*16384, bd, x, u, out, nullptr, nullptr);
}

// round 11
// speedup vs baseline: 1.3347x; 1.0792x over previous
#include <cuda_runtime.h>
#include <cuda_bf16.h>
#include <cuda_fp16.h>
#include <cstdint>
#include <math.h>

#define NROWS 32768
#define FDIM  128
#define KDIM  64
#define MNBR  32
#define NTILES (NROWS/4)

// Scratch (allocation-free rule: __device__ globals)
__device__ float g_xi [NROWS*FDIM];
__device__ float g_xjp[NROWS*FDIM];
__device__ float g_m0 [NROWS*FDIM];
__device__ float g_m1 [NROWS*FDIM];
__device__ __align__(16) __half g_wfH[7*16384];
__device__ __align__(16) __half g_wfL[7*16384];
__device__ __align__(16) __half g_tf[NROWS*FDIM];   // raw t (fp16)
__device__ __align__(16) __half g_sf[NROWS*FDIM];   // ssp-activation (fp16)

__device__ __forceinline__ float sspf(float a) {
    return fmaxf(a, 0.0f) + log1pf(expf(-fabsf(a))) - 0.69314718055994530942f;
}

// ---------------- mma.sync / cp.async helpers ----------------
__device__ __forceinline__ uint32_t s2u(const void* p) {
    uint32_t a;
    asm("{ .reg .u64 t; cvta.to.shared.u64 t, %1; cvt.u32.u64 %0, t; }" : "=r"(a) : "l"(p));
    return a;
}

#define LDM_X4(r, addr) \
    asm volatile("ldmatrix.sync.aligned.m8n8.x4.shared.b16 {%0,%1,%2,%3}, [%4];" \
        : "=r"((r)[0]), "=r"((r)[1]), "=r"((r)[2]), "=r"((r)[3]) : "r"(addr))

#define MMA_F16(d, a, b0, b1) \
    asm volatile("mma.sync.aligned.m16n8k16.row.col.f32.f16.f16.f32 " \
        "{%0,%1,%2,%3}, {%4,%5,%6,%7}, {%8,%9}, {%0,%1,%2,%3};" \
        : "+f"((d)[0]), "+f"((d)[1]), "+f"((d)[2]), "+f"((d)[3]) \
        : "r"((a)[0]), "r"((a)[1]), "r"((a)[2]), "r"((a)[3]), "r"(b0), "r"(b1))

#define CP16(dst, src) \
    asm volatile("cp.async.cg.shared.global [%0], [%1], 16;" :: "r"(dst), "l"(src) : "memory")
#define CP_COMMIT() asm volatile("cp.async.commit_group;" ::: "memory")
#define CP_WAIT0()  asm volatile("cp.async.wait_group 0;" ::: "memory")

__device__ __forceinline__ void f16_split4(float4 v, __half* H, __half* L) {
    __half h0 = __float2half_rn(v.x), h1 = __float2half_rn(v.y),
           h2 = __float2half_rn(v.z), h3 = __float2half_rn(v.w);
    *(__half2*)(H)     = __half2(h0, h1);
    *(__half2*)(H + 2) = __half2(h2, h3);
    *(__half2*)(L)     = __half2(__float2half_rn(v.x - __half2float(h0)),
                                 __float2half_rn(v.y - __half2float(h1)));
    *(__half2*)(L + 2) = __half2(__float2half_rn(v.z - __half2float(h2)),
                                 __float2half_rn(v.w - __half2float(h3)));
}

// ---------------- weight pre-split: 7 matrices of 128x128 (fp16 hi/lo, exact) ----------------
__global__ void __launch_bounds__(256) prep_w(
    const float* __restrict__ wi, const float* __restrict__ wj,
    const float* __restrict__ rw1, const float* __restrict__ rw2,
    const float* __restrict__ wd,
    __half* __restrict__ WH, __half* __restrict__ WL)
{
    int idx = blockIdx.x * 256 + threadIdx.x;
    int mat = idx >> 12, off = idx & 4095;
    const float* src;
    switch (mat) {
        case 0: src = wi; break;
        case 1: src = wj; break;
        case 2: src = rw1; break;
        case 3: src = rw2; break;
        case 4: src = rw1 + 16384; break;
        case 5: src = rw2 + 16384; break;
        default: src = wd; break;
    }
    float4 v = ((const float4*)src)[off];
    size_t d = (size_t)mat * 16384 + (size_t)off * 4;
    f16_split4(v, WH + d, WL + d);
}

// =================================================================================
// Tensor-core row GEMM: fp16 2-pass (W = hi/lo exact, A = single fp16).
// 256 threads, 64x128 tile, 2 CTAs/SM.
// =================================================================================
#define TG_WH    0u
#define TG_WL    34816u
#define TG_U     69632u           // A fp16 64x136x2=17408 | slab 64x132 fp32 = 33792
#define TG_AH    TG_U
#define TG_BIAS  103424u
#define TG_MUL   103936u
#define TG_TOTAL 104448u
#define TG_SLABS 132

template<int AMODE, bool ADD, bool MULVEC, bool OUTF32, bool OUTSPLIT, bool OSSP>
__global__ __launch_bounds__(256, 2) void tg2(
    const void* __restrict__ aSrc,
    const __half* __restrict__ wHsrc, const __half* __restrict__ wLsrc,
    const float* __restrict__ bias, const float* __restrict__ addp,
    const float* __restrict__ mulv, float* __restrict__ outf,
    __half* __restrict__ oH)
{
    extern __shared__ char smem[];
    __half* AH = (__half*)(smem + TG_AH);
    float* slab = (float*)(smem + TG_U);
    float* b_sm = (float*)(smem + TG_BIAS);
    float* u_sm = (float*)(smem + TG_MUL);

    const int tid = threadIdx.x;
    const int wid = tid >> 5, lid = tid & 31;
    const uint32_t sb = s2u(smem);

    // W: pure copy of pre-split fp16 (2048 uint4 per buffer)
    #pragma unroll
    for (int i = 0; i < 8; i++) {
        int idx = tid + 256 * i;
        int row = idx >> 4, c8 = idx & 15;
        *(uint4*)(smem + TG_WH + row * 272 + c8 * 16) = ((const uint4*)wHsrc)[idx];
        *(uint4*)(smem + TG_WL + row * 272 + c8 * 16) = ((const uint4*)wLsrc)[idx];
    }
    if (tid < 128) {
        b_sm[tid] = bias[tid];
        u_sm[tid] = MULVEC ? mulv[tid] : 0.0f;
    }

    const int r0 = blockIdx.x * 64;

    if (AMODE == 0) {
        // fp32 -> ssp -> single fp16
        #pragma unroll
        for (int i = 0; i < 8; i++) {
            int fidx = tid + 256 * i;            // float4 over 2048
            float4 v = ((const float4*)((const float*)aSrc + (size_t)r0 * FDIM))[fidx];
            v.x = sspf(v.x); v.y = sspf(v.y); v.z = sspf(v.z); v.w = sspf(v.w);
            int row = fidx >> 5, c = (fidx & 31) * 4;
            __half* dst = AH + row * 136 + c;
            *(__half2*)(dst)     = __floats2half2_rn(v.x, v.y);
            *(__half2*)(dst + 2) = __floats2half2_rn(v.z, v.w);
        }
    } else {
        // pre-converted single fp16: pure copy (1024 uint4)
        const uint4* a4 = (const uint4*)((const __half*)aSrc + (size_t)r0 * FDIM);
        #pragma unroll
        for (int i = 0; i < 4; i++) {
            int idx = tid + 256 * i;
            int row = idx >> 4, c8 = idx & 15;
            *(uint4*)(smem + TG_AH + row * 272 + c8 * 16) = a4[idx];
        }
    }
    __syncthreads();

    const uint32_t aL_off = (((lid & 7) + (lid & 8)) * 136 + ((lid & 16) ? 8 : 0)) * 2;
    const uint32_t bL_off = (((lid & 7) + ((lid & 16) >> 1)) * 136 + ((lid & 8) ? 8 : 0)) * 2;
    const int wr = wid & 1, wc = wid >> 1;

    float acc[2][4][4];
    #pragma unroll
    for (int mt = 0; mt < 2; mt++)
        #pragma unroll
        for (int nb = 0; nb < 4; nb++)
            #pragma unroll
            for (int c = 0; c < 4; c++) acc[mt][nb][c] = 0.f;

    #pragma unroll
    for (int kk = 0; kk < 8; kk++) {
        const uint32_t kb = (uint32_t)kk * 32;
        uint32_t ah[2][4], bh[2][4], bl[2][4];
        #pragma unroll
        for (int mt = 0; mt < 2; mt++) {
            uint32_t ro = (uint32_t)(32*wr + 16*mt) * 272 + kb;
            LDM_X4(ah[mt], sb + TG_AH + aL_off + ro);
        }
        #pragma unroll
        for (int np = 0; np < 2; np++) {
            uint32_t no = (uint32_t)(32*wc + 16*np) * 272 + kb;
            LDM_X4(bh[np], sb + TG_WH + bL_off + no);
            LDM_X4(bl[np], sb + TG_WL + bL_off + no);
        }
        #pragma unroll
        for (int mt = 0; mt < 2; mt++)
            #pragma unroll
            for (int np = 0; np < 2; np++) {
                MMA_F16(acc[mt][2*np],   ah[mt], bh[np][0], bh[np][1]);
                MMA_F16(acc[mt][2*np+1], ah[mt], bh[np][2], bh[np][3]);
                MMA_F16(acc[mt][2*np],   ah[mt], bl[np][0], bl[np][1]);
                MMA_F16(acc[mt][2*np+1], ah[mt], bl[np][2], bl[np][3]);
            }
    }
    __syncthreads();   // A reads done -> union becomes slab

    {
        const int g = lid >> 2, t = lid & 3;
        #pragma unroll
        for (int mt = 0; mt < 2; mt++)
            #pragma unroll
            for (int nb = 0; nb < 4; nb++) {
                int e = 32*wr + 16*mt + g;
                int c = 32*wc + 8*nb + 2*t;
                *(float2*)&slab[e * TG_SLABS + c] = make_float2(acc[mt][nb][0], acc[mt][nb][1]);
                *(float2*)&slab[(e+8) * TG_SLABS + c] = make_float2(acc[mt][nb][2], acc[mt][nb][3]);
            }
    }
    __syncthreads();

    #pragma unroll
    for (int i = 0; i < 32; i++) {
        int idx = tid + 256 * i;
        int row = idx >> 7, col = idx & 127;
        size_t gpos = (size_t)(r0 + row) * FDIM + col;
        float o = slab[row * TG_SLABS + col] + b_sm[col];
        if (ADD) {
            float av = addp[gpos];
            o += MULVEC ? av * u_sm[col] : av;
        }
        if (OUTF32) outf[gpos] = o;
        if (OUTSPLIT) {
            float s = OSSP ? sspf(o) : o;
            oH[gpos] = __float2half_rn(s);
        }
    }
}

// =================================================================================
// Fused edge-filter GEMM + gather + attention — cp.async pipelined, fp16 2-pass MMA.
// =================================================================================
#define OFF_BH   0u
#define OFF_BL   18432u
#define OFF_U    36864u          // AH fp16 (18432) | slab 128x132 fp32 (67584) union
#define OFF_AH   OFF_U
#define OFF_XPB  104448u         // gathered xjp rows [128][128] fp32 = 65536
#define OFF_STG  169984u         // rbf raw staging 32768
#define OFF_XI2  202752u         // 2 x 2048 (double-buffered xi)
#define OFF_PART 206848u         // float[2048]
#define OFF_ATT  215040u         // float[128]
#define OFF_JB   215552u         // 2 x 512 (double-buffered jidx)
#define SM_TOTAL 216576u
#define SLAB_STRIDE 132

__global__ void __launch_bounds__(512, 1) attn_mma(
    const float* __restrict__ rbf, const int* __restrict__ idxj,
    const float* __restrict__ k2f, const float* __restrict__ xi,
    const float* __restrict__ xjp, float* __restrict__ mout,
    __half* __restrict__ oH)
{
    extern __shared__ char smem[];
    __half* AH = (__half*)(smem + OFF_AH);
    __half* BH = (__half*)(smem + OFF_BH);
    __half* BL = (__half*)(smem + OFF_BL);
    float* slab   = (float*)(smem + OFF_U);
    float* xpb    = (float*)(smem + OFF_XPB);
    float* part   = (float*)(smem + OFF_PART);
    float* att_sm = (float*)(smem + OFF_ATT);

    const int tid = threadIdx.x;
    const int wid = tid >> 5, lid = tid & 31;
    const uint32_t sb = s2u(smem);

    // B = k2f, fp16 hi/lo split, once
    #pragma unroll
    for (int i = 0; i < 4; i++) {
        int fidx = tid + 512 * i;
        float4 v = ((const float4*)k2f)[fidx];
        int row = fidx >> 4, c = (fidx & 15) * 4;
        f16_split4(v, BH + row*72 + c, BL + row*72 + c);
    }

    const uint32_t aL = ((((lid & 7) + (lid & 8)) * 72) + ((lid & 16) ? 8 : 0)) * 2;
    const uint32_t bL = ((((lid & 7) + ((lid & 16) >> 1)) * 72) + ((lid & 8) ? 8 : 0)) * 2;
    const int wr = wid & 3, wc = wid >> 2;
    const int f  = tid & 127;
    const int q  = f >> 5;
    const int e0 = tid >> 7;
    const int stride = gridDim.x;

    auto stage = [&](int tile, int sel) {
        const char* rsrc = (const char*)(rbf + (size_t)tile * 8192);
        #pragma unroll
        for (int i = 0; i < 4; i++) {
            uint32_t o = (uint32_t)(tid + 512 * i) * 16u;
            CP16(sb + OFF_STG + o, rsrc + o);
        }
        if (tid < 128)
            CP16(sb + OFF_XI2 + (uint32_t)sel * 2048u + tid * 16u,
                 (const char*)(xi + (size_t)tile * 512) + tid * 16);
        if (tid < 32)
            CP16(sb + OFF_JB + (uint32_t)sel * 512u + tid * 16u,
                 (const char*)(idxj + tile * 128) + tid * 16);
    };
    auto gather = [&](int sel) {
        const int* jb = (const int*)(smem + OFF_JB + sel * 512);
        #pragma unroll
        for (int r = 0; r < 8; r++) {
            int e = wid * 8 + r;
            int j = jb[e];
            CP16(sb + OFF_XPB + (uint32_t)e * 512u + lid * 16u,
                 (const char*)(xjp + (size_t)j * FDIM) + lid * 16);
        }
    };

    int cur = 0;
    stage(blockIdx.x, 0);
    CP_COMMIT();
    CP_WAIT0();
    __syncthreads();
    gather(0);
    CP_COMMIT();

    for (int tile = blockIdx.x; tile < NTILES; tile += stride) {
        const int n0 = tile * 4;
        const int nxt = tile + stride;
        const bool has = nxt < NTILES;

        // A: fp32 staging -> single fp16
        #pragma unroll
        for (int i = 0; i < 4; i++) {
            int fidx = tid + 512 * i;
            float4 v = *(const float4*)(smem + OFF_STG + (uint32_t)fidx * 16u);
            int row = fidx >> 4, c = (fidx & 15) * 4;
            __half* dst = AH + row*72 + c;
            *(__half2*)(dst)     = __floats2half2_rn(v.x, v.y);
            *(__half2*)(dst + 2) = __floats2half2_rn(v.z, v.w);
        }
        if (has) stage(nxt, cur ^ 1);
        CP_COMMIT();
        __syncthreads();

        // MMA 128x128x64: D = A*(Bh+Bl), fp16 2-pass
        float acc[2][4][4];
        #pragma unroll
        for (int mt = 0; mt < 2; mt++)
            #pragma unroll
            for (int nb = 0; nb < 4; nb++)
                #pragma unroll
                for (int c = 0; c < 4; c++) acc[mt][nb][c] = 0.f;

        #pragma unroll
        for (int kk = 0; kk < 4; kk++) {
            const uint32_t kb = (uint32_t)kk * 32;
            uint32_t ah[2][4], bh[2][4], bl[2][4];
            #pragma unroll
            for (int mt = 0; mt < 2; mt++) {
                uint32_t ro = (uint32_t)(32*wr + 16*mt) * 144 + kb;
                LDM_X4(ah[mt], sb + OFF_AH + aL + ro);
            }
            #pragma unroll
            for (int np = 0; np < 2; np++) {
                uint32_t no = (uint32_t)(32*wc + 16*np) * 144 + kb;
                LDM_X4(bh[np], sb + OFF_BH + bL + no);
                LDM_X4(bl[np], sb + OFF_BL + bL + no);
            }
            #pragma unroll
            for (int mt = 0; mt < 2; mt++)
                #pragma unroll
                for (int np = 0; np < 2; np++) {
                    MMA_F16(acc[mt][2*np],   ah[mt], bh[np][0], bh[np][1]);
                    MMA_F16(acc[mt][2*np+1], ah[mt], bh[np][2], bh[np][3]);
                    MMA_F16(acc[mt][2*np],   ah[mt], bl[np][0], bl[np][1]);
                    MMA_F16(acc[mt][2*np+1], ah[mt], bl[np][2], bl[np][3]);
                }
        }
        __syncthreads();   // A dead -> slab

        {
            const int g = lid >> 2, t = lid & 3;
            #pragma unroll
            for (int mt = 0; mt < 2; mt++)
                #pragma unroll
                for (int nb = 0; nb < 4; nb++) {
                    int e = 32*wr + 16*mt + g;
                    int c = 32*wc + 8*nb + 2*t;
                    *(float2*)&slab[e * SLAB_STRIDE + c] =
                        make_float2(acc[mt][nb][0], acc[mt][nb][1]);
                    *(float2*)&slab[(e + 8) * SLAB_STRIDE + c] =
                        make_float2(acc[mt][nb][2], acc[mt][nb][3]);
                }
        }
        CP_WAIT0();
        __syncthreads();

        const float* xi_c = (const float*)(smem + OFF_XI2 + (uint32_t)cur * 2048u);

        float xp[32];
        float lacc[4] = {0.f, 0.f, 0.f, 0.f};
        #pragma unroll
        for (int i = 0; i < 32; i++) {
            const int e = 4*i + e0;
            const int a = i >> 3;
            const int m = e & 31;
            float p = slab[e * SLAB_STRIDE + f] * xpb[e * FDIM + f];
            xp[i] = p;
            lacc[a] += xi_c[a * FDIM + 4*m + q] * p;
        }
        #pragma unroll
        for (int a = 0; a < 4; a++)
            part[wid * 128 + a * 32 + lid] = lacc[a];
        __syncthreads();

        if (wid < 4) {
            float lg = 0.f;
            #pragma unroll
            for (int w2 = 0; w2 < 16; w2++) lg += part[w2 * 128 + wid * 32 + lid];
            float mx = lg;
            #pragma unroll
            for (int o = 16; o; o >>= 1) mx = fmaxf(mx, __shfl_xor_sync(0xffffffffu, mx, o));
            float ex = expf(lg - mx);
            float smv = ex;
            #pragma unroll
            for (int o = 16; o; o >>= 1) smv += __shfl_xor_sync(0xffffffffu, smv, o);
            att_sm[wid * 32 + lid] = ex / smv;
        }
        __syncthreads();

        float pacc[4] = {0.f, 0.f, 0.f, 0.f};
        #pragma unroll
        for (int i = 0; i < 32; i++) {
            const int e = 4*i + e0;
            const int a = i >> 3;
            const int m = e & 31;
            pacc[a] += att_sm[a * 32 + m] * xp[i];
        }
        #pragma unroll
        for (int a = 0; a < 4; a++)
            part[e0 * 512 + a * 128 + f] = pacc[a];
        __syncthreads();

        {
            size_t gpos = (size_t)n0 * FDIM + tid;
            float mv = xi_c[tid]
                + part[tid] + part[512 + tid] + part[1024 + tid] + part[1536 + tid];
            mout[gpos] = mv;
            oH[gpos] = __float2half_rn(sspf(mv));
        }

        if (has) gather(cur ^ 1);
        CP_COMMIT();
        __syncthreads();
        cur ^= 1;
    }
}

extern "C" void kernel_launch(void* const* d_in, const int* in_sizes, int n_in,
                              void* d_out, int out_size)
{
    const float* x    = (const float*)d_in[0];
    const float* rbf  = (const float*)d_in[1];
    const int*   idxj = (const int*)  d_in[3];
    const float* k2f  = (const float*)d_in[4];
    const float* wi   = (const float*)d_in[5];
    const float* bi   = (const float*)d_in[6];
    const float* wj   = (const float*)d_in[7];
    const float* bj   = (const float*)d_in[8];
    const float* rw1  = (const float*)d_in[9];
    const float* rb1  = (const float*)d_in[10];
    const float* rw2  = (const float*)d_in[11];
    const float* rb2  = (const float*)d_in[12];
    const float* wd   = (const float*)d_in[13];
    const float* bd   = (const float*)d_in[14];
    const float* u    = (const float*)d_in[15];
    float* out = (float*)d_out;

    float *xi_p, *xjp_p, *m0_p, *m1_p;
    __half *wfH, *wfL, *tf, *sf;
    cudaGetSymbolAddress((void**)&xi_p,  g_xi);
    cudaGetSymbolAddress((void**)&xjp_p, g_xjp);
    cudaGetSymbolAddress((void**)&m0_p,  g_m0);
    cudaGetSymbolAddress((void**)&m1_p,  g_m1);
    cudaGetSymbolAddress((void**)&wfH,   g_wfH);
    cudaGetSymbolAddress((void**)&wfL,   g_wfL);
    cudaGetSymbolAddress((void**)&tf,    g_tf);
    cudaGetSymbolAddress((void**)&sf,    g_sf);

    static int nsm = 0;
    if (nsm == 0) {
        cudaDeviceGetAttribute(&nsm, cudaDevAttrMultiProcessorCount, 0);
        if (nsm <= 0) nsm = 148;
        cudaFuncSetAttribute(attn_mma, cudaFuncAttributeMaxDynamicSharedMemorySize, SM_TOTAL);
        cudaFuncSetAttribute(tg2<0,false,false,true,false,false>, cudaFuncAttributeMaxDynamicSharedMemorySize, TG_TOTAL);
        cudaFuncSetAttribute(tg2<1,false,false,false,true,false>, cudaFuncAttributeMaxDynamicSharedMemorySize, TG_TOTAL);
        cudaFuncSetAttribute(tg2<1,true,false,true,true,true>,    cudaFuncAttributeMaxDynamicSharedMemorySize, TG_TOTAL);
        cudaFuncSetAttribute(tg2<1,true,false,false,true,true>,   cudaFuncAttributeMaxDynamicSharedMemorySize, TG_TOTAL);
        cudaFuncSetAttribute(tg2<1,true,true,true,false,false>,   cudaFuncAttributeMaxDynamicSharedMemorySize, TG_TOTAL);
    }

    const int TG_GRID = NROWS / 64;   // 512

    prep_w<<<112, 256>>>(wi, wj, rw1, rw2, wd, wfH, wfL);

    // xi = ssp(x)@wi.T+bi ; xjp = ssp(x)@wj.T+bj
    tg2<0,false,false,true,false,false><<<TG_GRID, 256, TG_TOTAL>>>(
        x, wfH, wfL, bi, nullptr, nullptr, xi_p, nullptr);
    tg2<0,false,false,true,false,false><<<TG_GRID, 256, TG_TOTAL>>>(
        x, wfH + 16384, wfL + 16384, bj, nullptr, nullptr, xjp_p, nullptr);

    // m0 = attention; emits fp16 ssp(m0) -> sf
    attn_mma<<<nsm, 512, SM_TOTAL>>>(rbf, idxj, k2f, xi_p, xjp_p, m0_p, sf);

    // res block 0
    tg2<1,false,false,false,true,false><<<TG_GRID, 256, TG_TOTAL>>>(
        sf, wfH + 2*16384, wfL + 2*16384, rb1, nullptr, nullptr, nullptr, tf);
    tg2<1,true,false,true,true,true><<<TG_GRID, 256, TG_TOTAL>>>(
        tf, wfH + 3*16384, wfL + 3*16384, rb2, m0_p, nullptr, m1_p, sf);

    // res block 1
    tg2<1,false,false,false,true,false><<<TG_GRID, 256, TG_TOTAL>>>(
        sf, wfH + 4*16384, wfL + 4*16384, rb1 + FDIM, nullptr, nullptr, nullptr, tf);
    tg2<1,true,false,false,true,true><<<TG_GRID, 256, TG_TOTAL>>>(
        tf, wfH + 5*16384, wfL + 5*16384, rb2 + FDIM, m1_p, nullptr, nullptr, sf);

    // out = u*x + ssp(m2)@wd+bd
    tg2<1,true,true,true,false,false><<<TG_GRID, 256, TG_TOTAL>>>(
        sf, wfH + 6*16384, wfL + 6*16384, bd, x, u, out, nullptr);
}

// round 12
// speedup vs baseline: 1.4316x; 1.0726x over previous
#include <cuda_runtime.h>
#include <cuda_bf16.h>
#include <cuda_fp16.h>
#include <cstdint>
#include <math.h>

#define NROWS 32768
#define FDIM  128
#define KDIM  64
#define MNBR  32
#define NTILES (NROWS/4)

// Scratch (allocation-free rule: __device__ globals)
__device__ float g_xi [NROWS*FDIM];
__device__ float g_m0 [NROWS*FDIM];
__device__ float g_m1 [NROWS*FDIM];
__device__ __align__(16) __half g_xjpH[NROWS*FDIM];  // xjp in fp16 (gather table)
__device__ __align__(16) __half g_wfH[7*16384];
__device__ __align__(16) __half g_wfL[7*16384];
__device__ __align__(16) __half g_tf[NROWS*FDIM];    // raw t (fp16)
__device__ __align__(16) __half g_sf[NROWS*FDIM];    // ssp-activation (fp16)

__device__ __forceinline__ float sspf(float a) {
    return fmaxf(a, 0.0f) + log1pf(expf(-fabsf(a))) - 0.69314718055994530942f;
}

// ---------------- mma.sync / cp.async helpers ----------------
__device__ __forceinline__ uint32_t s2u(const void* p) {
    uint32_t a;
    asm("{ .reg .u64 t; cvta.to.shared.u64 t, %1; cvt.u32.u64 %0, t; }" : "=r"(a) : "l"(p));
    return a;
}

#define LDM_X4(r, addr) \
    asm volatile("ldmatrix.sync.aligned.m8n8.x4.shared.b16 {%0,%1,%2,%3}, [%4];" \
        : "=r"((r)[0]), "=r"((r)[1]), "=r"((r)[2]), "=r"((r)[3]) : "r"(addr))

#define MMA_F16(d, a, b0, b1) \
    asm volatile("mma.sync.aligned.m16n8k16.row.col.f32.f16.f16.f32 " \
        "{%0,%1,%2,%3}, {%4,%5,%6,%7}, {%8,%9}, {%0,%1,%2,%3};" \
        : "+f"((d)[0]), "+f"((d)[1]), "+f"((d)[2]), "+f"((d)[3]) \
        : "r"((a)[0]), "r"((a)[1]), "r"((a)[2]), "r"((a)[3]), "r"(b0), "r"(b1))

#define CP16(dst, src) \
    asm volatile("cp.async.cg.shared.global [%0], [%1], 16;" :: "r"(dst), "l"(src) : "memory")
#define CP_COMMIT() asm volatile("cp.async.commit_group;" ::: "memory")
#define CP_WAIT0()  asm volatile("cp.async.wait_group 0;" ::: "memory")

__device__ __forceinline__ void f16_split4(float4 v, __half* H, __half* L) {
    __half h0 = __float2half_rn(v.x), h1 = __float2half_rn(v.y),
           h2 = __float2half_rn(v.z), h3 = __float2half_rn(v.w);
    *(__half2*)(H)     = __half2(h0, h1);
    *(__half2*)(H + 2) = __half2(h2, h3);
    *(__half2*)(L)     = __half2(__float2half_rn(v.x - __half2float(h0)),
                                 __float2half_rn(v.y - __half2float(h1)));
    *(__half2*)(L + 2) = __half2(__float2half_rn(v.z - __half2float(h2)),
                                 __float2half_rn(v.w - __half2float(h3)));
}

// ---------------- weight pre-split: 7 matrices of 128x128 (fp16 hi/lo, exact) ----------------
__global__ void __launch_bounds__(256) prep_w(
    const float* __restrict__ wi, const float* __restrict__ wj,
    const float* __restrict__ rw1, const float* __restrict__ rw2,
    const float* __restrict__ wd,
    __half* __restrict__ WH, __half* __restrict__ WL)
{
    int idx = blockIdx.x * 256 + threadIdx.x;
    int mat = idx >> 12, off = idx & 4095;
    const float* src;
    switch (mat) {
        case 0: src = wi; break;
        case 1: src = wj; break;
        case 2: src = rw1; break;
        case 3: src = rw2; break;
        case 4: src = rw1 + 16384; break;
        case 5: src = rw2 + 16384; break;
        default: src = wd; break;
    }
    float4 v = ((const float4*)src)[off];
    size_t d = (size_t)mat * 16384 + (size_t)off * 4;
    f16_split4(v, WH + d, WL + d);
}

// =================================================================================
// Tensor-core row GEMM: fp16 2-pass (W = hi/lo exact, A = single fp16).
// 256 threads, 64x128 tile, 2 CTAs/SM.
// =================================================================================
#define TG_WH    0u
#define TG_WL    34816u
#define TG_U     69632u           // A fp16 64x136x2=17408 | slab 64x132 fp32 = 33792
#define TG_AH    TG_U
#define TG_BIAS  103424u
#define TG_MUL   103936u
#define TG_TOTAL 104448u
#define TG_SLABS 132

template<int AMODE, bool ADD, bool MULVEC, bool OUTF32, bool OUTSPLIT, bool OSSP>
__global__ __launch_bounds__(256, 2) void tg2(
    const void* __restrict__ aSrc,
    const __half* __restrict__ wHsrc, const __half* __restrict__ wLsrc,
    const float* __restrict__ bias, const float* __restrict__ addp,
    const float* __restrict__ mulv, float* __restrict__ outf,
    __half* __restrict__ oH)
{
    extern __shared__ char smem[];
    __half* AH = (__half*)(smem + TG_AH);
    float* slab = (float*)(smem + TG_U);
    float* b_sm = (float*)(smem + TG_BIAS);
    float* u_sm = (float*)(smem + TG_MUL);

    const int tid = threadIdx.x;
    const int wid = tid >> 5, lid = tid & 31;
    const uint32_t sb = s2u(smem);

    // W: pure copy of pre-split fp16 (2048 uint4 per buffer)
    #pragma unroll
    for (int i = 0; i < 8; i++) {
        int idx = tid + 256 * i;
        int row = idx >> 4, c8 = idx & 15;
        *(uint4*)(smem + TG_WH + row * 272 + c8 * 16) = ((const uint4*)wHsrc)[idx];
        *(uint4*)(smem + TG_WL + row * 272 + c8 * 16) = ((const uint4*)wLsrc)[idx];
    }
    if (tid < 128) {
        b_sm[tid] = bias[tid];
        u_sm[tid] = MULVEC ? mulv[tid] : 0.0f;
    }

    const int r0 = blockIdx.x * 64;

    if (AMODE == 0) {
        // fp32 -> ssp -> single fp16
        #pragma unroll
        for (int i = 0; i < 8; i++) {
            int fidx = tid + 256 * i;            // float4 over 2048
            float4 v = ((const float4*)((const float*)aSrc + (size_t)r0 * FDIM))[fidx];
            v.x = sspf(v.x); v.y = sspf(v.y); v.z = sspf(v.z); v.w = sspf(v.w);
            int row = fidx >> 5, c = (fidx & 31) * 4;
            __half* dst = AH + row * 136 + c;
            *(__half2*)(dst)     = __floats2half2_rn(v.x, v.y);
            *(__half2*)(dst + 2) = __floats2half2_rn(v.z, v.w);
        }
    } else {
        // pre-converted single fp16: pure copy (1024 uint4)
        const uint4* a4 = (const uint4*)((const __half*)aSrc + (size_t)r0 * FDIM);
        #pragma unroll
        for (int i = 0; i < 4; i++) {
            int idx = tid + 256 * i;
            int row = idx >> 4, c8 = idx & 15;
            *(uint4*)(smem + TG_AH + row * 272 + c8 * 16) = a4[idx];
        }
    }
    __syncthreads();

    const uint32_t aL_off = (((lid & 7) + (lid & 8)) * 136 + ((lid & 16) ? 8 : 0)) * 2;
    const uint32_t bL_off = (((lid & 7) + ((lid & 16) >> 1)) * 136 + ((lid & 8) ? 8 : 0)) * 2;
    const int wr = wid & 1, wc = wid >> 1;

    float acc[2][4][4];
    #pragma unroll
    for (int mt = 0; mt < 2; mt++)
        #pragma unroll
        for (int nb = 0; nb < 4; nb++)
            #pragma unroll
            for (int c = 0; c < 4; c++) acc[mt][nb][c] = 0.f;

    #pragma unroll
    for (int kk = 0; kk < 8; kk++) {
        const uint32_t kb = (uint32_t)kk * 32;
        uint32_t ah[2][4], bh[2][4], bl[2][4];
        #pragma unroll
        for (int mt = 0; mt < 2; mt++) {
            uint32_t ro = (uint32_t)(32*wr + 16*mt) * 272 + kb;
            LDM_X4(ah[mt], sb + TG_AH + aL_off + ro);
        }
        #pragma unroll
        for (int np = 0; np < 2; np++) {
            uint32_t no = (uint32_t)(32*wc + 16*np) * 272 + kb;
            LDM_X4(bh[np], sb + TG_WH + bL_off + no);
            LDM_X4(bl[np], sb + TG_WL + bL_off + no);
        }
        #pragma unroll
        for (int mt = 0; mt < 2; mt++)
            #pragma unroll
            for (int np = 0; np < 2; np++) {
                MMA_F16(acc[mt][2*np],   ah[mt], bh[np][0], bh[np][1]);
                MMA_F16(acc[mt][2*np+1], ah[mt], bh[np][2], bh[np][3]);
                MMA_F16(acc[mt][2*np],   ah[mt], bl[np][0], bl[np][1]);
                MMA_F16(acc[mt][2*np+1], ah[mt], bl[np][2], bl[np][3]);
            }
    }
    __syncthreads();   // A reads done -> union becomes slab

    {
        const int g = lid >> 2, t = lid & 3;
        #pragma unroll
        for (int mt = 0; mt < 2; mt++)
            #pragma unroll
            for (int nb = 0; nb < 4; nb++) {
                int e = 32*wr + 16*mt + g;
                int c = 32*wc + 8*nb + 2*t;
                *(float2*)&slab[e * TG_SLABS + c] = make_float2(acc[mt][nb][0], acc[mt][nb][1]);
                *(float2*)&slab[(e+8) * TG_SLABS + c] = make_float2(acc[mt][nb][2], acc[mt][nb][3]);
            }
    }
    __syncthreads();

    #pragma unroll
    for (int i = 0; i < 32; i++) {
        int idx = tid + 256 * i;
        int row = idx >> 7, col = idx & 127;
        size_t gpos = (size_t)(r0 + row) * FDIM + col;
        float o = slab[row * TG_SLABS + col] + b_sm[col];
        if (ADD) {
            float av = addp[gpos];
            o += MULVEC ? av * u_sm[col] : av;
        }
        if (OUTF32) outf[gpos] = o;
        if (OUTSPLIT) {
            float s = OSSP ? sspf(o) : o;
            oH[gpos] = __float2half_rn(s);
        }
    }
}

// =================================================================================
// Fused edge-filter GEMM + gather + attention — cp.async pipelined, fp16 2-pass MMA,
// fp16 slab + fp16 gather table (halved smem traffic for both).
// =================================================================================
#define OFF_BH   0u              // 18432
#define OFF_BL   18432u          // 18432
#define OFF_U    36864u          // AH fp16 128x72x2=18432 | slab fp16 128x136x2=34816
#define OFF_AH   OFF_U
#define OFF_XPB  71680u          // gathered xjp fp16 [128][128] = 32768
#define OFF_STG  104448u         // rbf raw staging 32768
#define OFF_XI2  137216u         // 2 x 2048 (double-buffered xi, fp32)
#define OFF_PART 141312u         // float[2048]
#define OFF_ATT  149504u         // float[128]
#define OFF_JB   150016u         // 2 x 512 (double-buffered jidx)
#define SM_TOTAL 151040u
#define SLAB_H   136             // halves per slab row

__global__ void __launch_bounds__(512, 1) attn_mma(
    const float* __restrict__ rbf, const int* __restrict__ idxj,
    const float* __restrict__ k2f, const float* __restrict__ xi,
    const __half* __restrict__ xjph, float* __restrict__ mout,
    __half* __restrict__ oH)
{
    extern __shared__ char smem[];
    __half* AH = (__half*)(smem + OFF_AH);
    __half* BH = (__half*)(smem + OFF_BH);
    __half* BL = (__half*)(smem + OFF_BL);
    __half* slabh = (__half*)(smem + OFF_U);
    __half* xpbh  = (__half*)(smem + OFF_XPB);
    float* part   = (float*)(smem + OFF_PART);
    float* att_sm = (float*)(smem + OFF_ATT);

    const int tid = threadIdx.x;
    const int wid = tid >> 5, lid = tid & 31;
    const uint32_t sb = s2u(smem);

    // B = k2f, fp16 hi/lo split, once
    #pragma unroll
    for (int i = 0; i < 4; i++) {
        int fidx = tid + 512 * i;
        float4 v = ((const float4*)k2f)[fidx];
        int row = fidx >> 4, c = (fidx & 15) * 4;
        f16_split4(v, BH + row*72 + c, BL + row*72 + c);
    }

    const uint32_t aL = ((((lid & 7) + (lid & 8)) * 72) + ((lid & 16) ? 8 : 0)) * 2;
    const uint32_t bL = ((((lid & 7) + ((lid & 16) >> 1)) * 72) + ((lid & 8) ? 8 : 0)) * 2;
    const int wr = wid & 3, wc = wid >> 2;
    const int f  = tid & 127;
    const int q  = f >> 5;
    const int e0 = tid >> 7;
    const int stride = gridDim.x;

    auto stage = [&](int tile, int sel) {
        const char* rsrc = (const char*)(rbf + (size_t)tile * 8192);
        #pragma unroll
        for (int i = 0; i < 4; i++) {
            uint32_t o = (uint32_t)(tid + 512 * i) * 16u;
            CP16(sb + OFF_STG + o, rsrc + o);
        }
        if (tid < 128)
            CP16(sb + OFF_XI2 + (uint32_t)sel * 2048u + tid * 16u,
                 (const char*)(xi + (size_t)tile * 512) + tid * 16);
        if (tid < 32)
            CP16(sb + OFF_JB + (uint32_t)sel * 512u + tid * 16u,
                 (const char*)(idxj + tile * 128) + tid * 16);
    };
    // gather fp16 rows: each row = 256 B = 16 lanes x 16 B; 2 rows per warp-step
    auto gather = [&](int sel) {
        const int* jb = (const int*)(smem + OFF_JB + sel * 512);
        const int half_sel = lid >> 4;            // 0 or 1
        const uint32_t lane_off = (uint32_t)(lid & 15) * 16u;
        #pragma unroll
        for (int r = 0; r < 4; r++) {
            int e = wid * 8 + r * 2 + half_sel;
            int j = jb[e];
            CP16(sb + OFF_XPB + (uint32_t)e * 256u + lane_off,
                 (const char*)(xjph + (size_t)j * FDIM) + lane_off);
        }
    };

    int cur = 0;
    stage(blockIdx.x, 0);
    CP_COMMIT();
    CP_WAIT0();
    __syncthreads();
    gather(0);
    CP_COMMIT();

    for (int tile = blockIdx.x; tile < NTILES; tile += stride) {
        const int n0 = tile * 4;
        const int nxt = tile + stride;
        const bool has = nxt < NTILES;

        // A: fp32 staging -> single fp16
        #pragma unroll
        for (int i = 0; i < 4; i++) {
            int fidx = tid + 512 * i;
            float4 v = *(const float4*)(smem + OFF_STG + (uint32_t)fidx * 16u);
            int row = fidx >> 4, c = (fidx & 15) * 4;
            __half* dst = AH + row*72 + c;
            *(__half2*)(dst)     = __floats2half2_rn(v.x, v.y);
            *(__half2*)(dst + 2) = __floats2half2_rn(v.z, v.w);
        }
        if (has) stage(nxt, cur ^ 1);
        CP_COMMIT();
        __syncthreads();

        // MMA 128x128x64: D = A*(Bh+Bl), fp16 2-pass
        float acc[2][4][4];
        #pragma unroll
        for (int mt = 0; mt < 2; mt++)
            #pragma unroll
            for (int nb = 0; nb < 4; nb++)
                #pragma unroll
                for (int c = 0; c < 4; c++) acc[mt][nb][c] = 0.f;

        #pragma unroll
        for (int kk = 0; kk < 4; kk++) {
            const uint32_t kb = (uint32_t)kk * 32;
            uint32_t ah[2][4], bh[2][4], bl[2][4];
            #pragma unroll
            for (int mt = 0; mt < 2; mt++) {
                uint32_t ro = (uint32_t)(32*wr + 16*mt) * 144 + kb;
                LDM_X4(ah[mt], sb + OFF_AH + aL + ro);
            }
            #pragma unroll
            for (int np = 0; np < 2; np++) {
                uint32_t no = (uint32_t)(32*wc + 16*np) * 144 + kb;
                LDM_X4(bh[np], sb + OFF_BH + bL + no);
                LDM_X4(bl[np], sb + OFF_BL + bL + no);
            }
            #pragma unroll
            for (int mt = 0; mt < 2; mt++)
                #pragma unroll
                for (int np = 0; np < 2; np++) {
                    MMA_F16(acc[mt][2*np],   ah[mt], bh[np][0], bh[np][1]);
                    MMA_F16(acc[mt][2*np+1], ah[mt], bh[np][2], bh[np][3]);
                    MMA_F16(acc[mt][2*np],   ah[mt], bl[np][0], bl[np][1]);
                    MMA_F16(acc[mt][2*np+1], ah[mt], bl[np][2], bl[np][3]);
                }
        }
        __syncthreads();   // A dead -> fp16 slab

        {
            const int g = lid >> 2, t = lid & 3;
            #pragma unroll
            for (int mt = 0; mt < 2; mt++)
                #pragma unroll
                for (int nb = 0; nb < 4; nb++) {
                    int e = 32*wr + 16*mt + g;
                    int c = 32*wc + 8*nb + 2*t;
                    *(__half2*)&slabh[e * SLAB_H + c] =
                        __floats2half2_rn(acc[mt][nb][0], acc[mt][nb][1]);
                    *(__half2*)&slabh[(e + 8) * SLAB_H + c] =
                        __floats2half2_rn(acc[mt][nb][2], acc[mt][nb][3]);
                }
        }
        CP_WAIT0();
        __syncthreads();

        const float* xi_c = (const float*)(smem + OFF_XI2 + (uint32_t)cur * 2048u);

        float xp[32];
        float lacc[4] = {0.f, 0.f, 0.f, 0.f};
        #pragma unroll
        for (int i = 0; i < 32; i++) {
            const int e = 4*i + e0;
            const int a = i >> 3;
            const int m = e & 31;
            float p = __half2float(slabh[e * SLAB_H + f]) * __half2float(xpbh[e * 128 + f]);
            xp[i] = p;
            lacc[a] += xi_c[a * FDIM + 4*m + q] * p;
        }
        #pragma unroll
        for (int a = 0; a < 4; a++)
            part[wid * 128 + a * 32 + lid] = lacc[a];
        __syncthreads();

        if (wid < 4) {
            float lg = 0.f;
            #pragma unroll
            for (int w2 = 0; w2 < 16; w2++) lg += part[w2 * 128 + wid * 32 + lid];
            float mx = lg;
            #pragma unroll
            for (int o = 16; o; o >>= 1) mx = fmaxf(mx, __shfl_xor_sync(0xffffffffu, mx, o));
            float ex = expf(lg - mx);
            float smv = ex;
            #pragma unroll
            for (int o = 16; o; o >>= 1) smv += __shfl_xor_sync(0xffffffffu, smv, o);
            att_sm[wid * 32 + lid] = ex / smv;
        }
        __syncthreads();

        float pacc[4] = {0.f, 0.f, 0.f, 0.f};
        #pragma unroll
        for (int i = 0; i < 32; i++) {
            const int e = 4*i + e0;
            const int a = i >> 3;
            const int m = e & 31;
            pacc[a] += att_sm[a * 32 + m] * xp[i];
        }
        #pragma unroll
        for (int a = 0; a < 4; a++)
            part[e0 * 512 + a * 128 + f] = pacc[a];
        __syncthreads();

        {
            size_t gpos = (size_t)n0 * FDIM + tid;
            float mv = xi_c[tid]
                + part[tid] + part[512 + tid] + part[1024 + tid] + part[1536 + tid];
            mout[gpos] = mv;
            oH[gpos] = __float2half_rn(sspf(mv));
        }

        if (has) gather(cur ^ 1);
        CP_COMMIT();
        __syncthreads();
        cur ^= 1;
    }
}

extern "C" void kernel_launch(void* const* d_in, const int* in_sizes, int n_in,
                              void* d_out, int out_size)
{
    const float* x    = (const float*)d_in[0];
    const float* rbf  = (const float*)d_in[1];
    const int*   idxj = (const int*)  d_in[3];
    const float* k2f  = (const float*)d_in[4];
    const float* wi   = (const float*)d_in[5];
    const float* bi   = (const float*)d_in[6];
    const float* wj   = (const float*)d_in[7];
    const float* bj   = (const float*)d_in[8];
    const float* rw1  = (const float*)d_in[9];
    const float* rb1  = (const float*)d_in[10];
    const float* rw2  = (const float*)d_in[11];
    const float* rb2  = (const float*)d_in[12];
    const float* wd   = (const float*)d_in[13];
    const float* bd   = (const float*)d_in[14];
    const float* u    = (const float*)d_in[15];
    float* out = (float*)d_out;

    float *xi_p, *m0_p, *m1_p;
    __half *xjpH, *wfH, *wfL, *tf, *sf;
    cudaGetSymbolAddress((void**)&xi_p,  g_xi);
    cudaGetSymbolAddress((void**)&m0_p,  g_m0);
    cudaGetSymbolAddress((void**)&m1_p,  g_m1);
    cudaGetSymbolAddress((void**)&xjpH,  g_xjpH);
    cudaGetSymbolAddress((void**)&wfH,   g_wfH);
    cudaGetSymbolAddress((void**)&wfL,   g_wfL);
    cudaGetSymbolAddress((void**)&tf,    g_tf);
    cudaGetSymbolAddress((void**)&sf,    g_sf);

    static int nsm = 0;
    if (nsm == 0) {
        cudaDeviceGetAttribute(&nsm, cudaDevAttrMultiProcessorCount, 0);
        if (nsm <= 0) nsm = 148;
        cudaFuncSetAttribute(attn_mma, cudaFuncAttributeMaxDynamicSharedMemorySize, SM_TOTAL);
        cudaFuncSetAttribute(tg2<0,false,false,true,false,false>,  cudaFuncAttributeMaxDynamicSharedMemorySize, TG_TOTAL);
        cudaFuncSetAttribute(tg2<0,false,false,false,true,false>,  cudaFuncAttributeMaxDynamicSharedMemorySize, TG_TOTAL);
        cudaFuncSetAttribute(tg2<1,false,false,false,true,false>,  cudaFuncAttributeMaxDynamicSharedMemorySize, TG_TOTAL);
        cudaFuncSetAttribute(tg2<1,true,false,true,true,true>,     cudaFuncAttributeMaxDynamicSharedMemorySize, TG_TOTAL);
        cudaFuncSetAttribute(tg2<1,true,false,false,true,true>,    cudaFuncAttributeMaxDynamicSharedMemorySize, TG_TOTAL);
        cudaFuncSetAttribute(tg2<1,true,true,true,false,false>,    cudaFuncAttributeMaxDynamicSharedMemorySize, TG_TOTAL);
    }

    const int TG_GRID = NROWS / 64;   // 512

    prep_w<<<112, 256>>>(wi, wj, rw1, rw2, wd, wfH, wfL);

    // xi = ssp(x)@wi.T+bi (fp32) ; xjp = ssp(x)@wj.T+bj (fp16 gather table)
    tg2<0,false,false,true,false,false><<<TG_GRID, 256, TG_TOTAL>>>(
        x, wfH, wfL, bi, nullptr, nullptr, xi_p, nullptr);
    tg2<0,false,false,false,true,false><<<TG_GRID, 256, TG_TOTAL>>>(
        x, wfH + 16384, wfL + 16384, bj, nullptr, nullptr, nullptr, xjpH);

    // m0 = attention; emits fp16 ssp(m0) -> sf
    attn_mma<<<nsm, 512, SM_TOTAL>>>(rbf, idxj, k2f, xi_p, xjpH, m0_p, sf);

    // res block 0
    tg2<1,false,false,false,true,false><<<TG_GRID, 256, TG_TOTAL>>>(
        sf, wfH + 2*16384, wfL + 2*16384, rb1, nullptr, nullptr, nullptr, tf);
    tg2<1,true,false,true,true,true><<<TG_GRID, 256, TG_TOTAL>>>(
        tf, wfH + 3*16384, wfL + 3*16384, rb2, m0_p, nullptr, m1_p, sf);

    // res block 1
    tg2<1,false,false,false,true,false><<<TG_GRID, 256, TG_TOTAL>>>(
        sf, wfH + 4*16384, wfL + 4*16384, rb1 + FDIM, nullptr, nullptr, nullptr, tf);
    tg2<1,true,false,false,true,true><<<TG_GRID, 256, TG_TOTAL>>>(
        tf, wfH + 5*16384, wfL + 5*16384, rb2 + FDIM, m1_p, nullptr, nullptr, sf);

    // out = u*x + ssp(m2)@wd+bd
    tg2<1,true,true,true,false,false><<<TG_GRID, 256, TG_TOTAL>>>(
        sf, wfH + 6*16384, wfL + 6*16384, bd, x, u, out, nullptr);
}